// round 8
// baseline (speedup 1.0000x reference)
#include <cuda_runtime.h>
#include <math.h>

// Problem constants (fixed shapes from setup_inputs)
#define BS      4
#define NHEAD   8
#define HH_TOT  32          // BS*NHEAD
#define T_LEN   1024
#define CH      64
#define NOBJ    8

// flash tile config (v3 core: 256 threads)
#define QT      64          // q rows per block
#define KT      128         // k cols per tile
#define FTHREADS 256
// smem layout (floats): Qs[64][66] | KT_s/Ps[64][130] | Vs[128][64]
#define QS_OFF  0
#define KT_OFF  (64 * 66)                   // 4224
#define V_OFF   (KT_OFF + 64 * 130)         // 12544
#define SMEM_FLOATS (V_OFF + 128 * 64)      // 20736
#define SMEM_BYTES  (SMEM_FLOATS * 4)       // 82944

typedef unsigned long long ull;

// ---------------- f32x2 helpers ----------------
__device__ __forceinline__ ull pk2(float lo, float hi) {
    ull r; asm("mov.b64 %0, {%1, %2};" : "=l"(r) : "f"(lo), "f"(hi)); return r;
}
__device__ __forceinline__ void upk2(ull v, float& lo, float& hi) {
    asm("mov.b64 {%0, %1}, %2;" : "=f"(lo), "=f"(hi) : "l"(v));
}
__device__ __forceinline__ ull fma2(ull a, ull b, ull c) {
    ull d; asm("fma.rn.f32x2 %0, %1, %2, %3;" : "=l"(d) : "l"(a), "l"(b), "l"(c)); return d;
}
__device__ __forceinline__ ull mul2(ull a, ull b) {
    ull d; asm("mul.rn.f32x2 %0, %1, %2;" : "=l"(d) : "l"(a), "l"(b)); return d;
}

// ---------------- scratch (device globals; no allocs allowed) ----------------
__device__ float g_Qn[HH_TOT * T_LEN * CH];
__device__ float g_Kn[HH_TOT * T_LEN * CH];
__device__ float g_Vn[HH_TOT * T_LEN * CH];
__device__ float g_Qf[HH_TOT * T_LEN * CH];
__device__ float g_Kf[HH_TOT * T_LEN * CH];
__device__ float g_Vf[HH_TOT * T_LEN * CH];
__device__ float g_anull[HH_TOT * T_LEN * CH];
__device__ float g_afg[HH_TOT * T_LEN * CH];
__device__ int   g_regbox[BS * NOBJ * 4];   // i0,i1,j0,j1 (clamped to 32)
__device__ float g_cnt[BS * T_LEN];

// ---------------- prep: region boxes + per-token overlap counter ----------------
__global__ __launch_bounds__(256)
void prep_kernel(const float* __restrict__ bb) {
    __shared__ int sreg[BS * NOBJ][4];
    const int tid = threadIdx.x;
    if (tid < BS * NOBJ) {
        const float* p = bb + tid * 5;
        float x = p[0], y = p[1], w = p[2], h = p[3];
        int i0 = (int)fminf(31.0f, floorf(y * 32.0f));
        int j0 = (int)fminf(31.0f, floorf(x * 32.0f));
        int hh = (int)fmaxf(1.0f, ceilf(h * 32.0f));
        int ww = (int)fmaxf(1.0f, ceilf(w * 32.0f));
        int i1 = min(32, i0 + hh);
        int j1 = min(32, j0 + ww);
        g_regbox[tid * 4 + 0] = i0;  g_regbox[tid * 4 + 1] = i1;
        g_regbox[tid * 4 + 2] = j0;  g_regbox[tid * 4 + 3] = j1;
        sreg[tid][0] = i0; sreg[tid][1] = i1; sreg[tid][2] = j0; sreg[tid][3] = j1;
    }
    __syncthreads();
    for (int idx = tid; idx < BS * T_LEN; idx += blockDim.x) {
        int b = idx / T_LEN, t = idx % T_LEN;
        int i = t >> 5, j = t & 31;
        float c = 0.0f;
        #pragma unroll
        for (int o = 0; o < NOBJ; o++) {
            const int* r = sreg[b * NOBJ + o];
            if (i >= r[0] && i < r[1] && j >= r[2] && j < r[3]) c += 1.0f;
        }
        g_cnt[idx] = c;
    }
}

__global__ __launch_bounds__(256)
void zero_afg_kernel() {
    int i = blockIdx.x * 256 + threadIdx.x;          // float4 index
    float4* p = (float4*)g_afg;
    if (i < (HH_TOT * T_LEN * CH) / 4) p[i] = make_float4(0.f, 0.f, 0.f, 0.f);
}

// ---------------- combine: qkv split + prompt projection GEMM (f32x2) ----------------
__global__ __launch_bounds__(256)
void combine_kernel(const float* __restrict__ qkv, const float* __restrict__ nemb,
                    const float* __restrict__ pemb, const float* __restrict__ W) {
    __shared__ float Ws[64 * 65];
    __shared__ __align__(16) float Es[64 * 68];
    const int g   = blockIdx.x;            // 0..23
    const int t0  = blockIdx.y * 64;
    const int zv  = blockIdx.z;
    const int b   = zv >> 1, var = zv & 1;
    const int head = g / 3, part = g % 3;
    const int cg0  = g * 64;
    const float* emb = (var ? pemb : nemb) + b * 64 * 1024;
    const int tid = threadIdx.x;

    for (int i = tid; i < 4096; i += 256) {
        int c = i >> 6, e = i & 63;
        Ws[c * 65 + e] = W[(cg0 + c) * 64 + e];
    }
    for (int i = tid; i < 4096; i += 256) {
        int e = i >> 6, t = i & 63;
        Es[e * 68 + t] = emb[e * 1024 + t0 + t];
    }
    __syncthreads();

    const int c = tid & 63, tg = tid >> 6;   // tg 0..3, 16 t each
    ull acc2[8];
    #pragma unroll
    for (int i = 0; i < 8; i++) acc2[i] = 0ULL;

    #pragma unroll 4
    for (int e = 0; e < 64; e++) {
        float w = Ws[c * 65 + e];
        ull w2 = pk2(w, w);
        const ull* row = (const ull*)(Es + e * 68 + tg * 16);
        #pragma unroll
        for (int k = 0; k < 8; k++) acc2[k] = fma2(w2, row[k], acc2[k]);
    }
    __syncthreads();
    // reuse Es to stage the qkv tile (row = c, fast = t, coalesced reads)
    const float* qk = qkv + (size_t)b * 1536 * 1024 + (size_t)cg0 * 1024 + t0;
    for (int i = tid; i < 4096; i += 256) {
        int cc = i >> 6, t = i & 63;
        Es[cc * 68 + t] = qk[cc * 1024 + t];
    }
    __syncthreads();

    float* dst;
    if (var == 0) dst = (part == 0 ? g_Qn : (part == 1 ? g_Kn : g_Vn));
    else          dst = (part == 0 ? g_Qf : (part == 1 ? g_Kf : g_Vf));
    dst += (b * NHEAD + head) * T_LEN * CH;
    const float sc = (part == 0) ? 0.125f : 1.0f;   // scale^2 folded into Q
    #pragma unroll
    for (int k = 0; k < 8; k++) {
        float a0, a1;
        upk2(acc2[k], a0, a1);
        int t = tg * 16 + 2 * k;
        dst[(t0 + t)     * CH + c] = (a0 + Es[c * 68 + t])     * sc;
        dst[(t0 + t + 1) * CH + c] = (a1 + Es[c * 68 + t + 1]) * sc;
    }
}

// ---------------- flash v3 core ----------------
// 256 threads. rowg = tid>>5 (warp id, 8 rows each), colg = tid&31.
// QK: thread owns 8 rows x 4 s-cols (2 f32x2 pairs). PV: 8 rows x 1 ch-pair.
// Each warp owns ALL 128 cols of its 8 rows -> Q/P reads are warp broadcasts.

__global__ __launch_bounds__(FTHREADS, 2)
void flash_null_kernel() {
    extern __shared__ float sm[];
    const int bh = blockIdx.y;
    const int q0 = blockIdx.x * QT;
    const float* Qp = g_Qn + (size_t)bh * T_LEN * CH;
    const float* Kp = g_Kn + (size_t)bh * T_LEN * CH;
    const float* Vp = g_Vn + (size_t)bh * T_LEN * CH;
    const int tid = threadIdx.x;
    const int rowg = tid >> 5, colg = tid & 31;
    const int r0 = rowg * 8;
    const int s0 = colg * 4;
    const int ch0 = colg * 2;

    int pcol[2];
    #pragma unroll
    for (int j = 0; j < 2; j++) {
        int s = s0 + 2 * j;
        pcol[j] = s ^ (((s >> 5) & 3) << 1);
    }
    const int vch = ch0 ^ (((ch0 >> 5) & 1) << 1);

    {   // load Q tile (coalesced float4 -> padded rows of 66)
        const float4* Qg = (const float4*)(Qp + (size_t)q0 * CH);
        for (int idx = tid; idx < QT * 16; idx += FTHREADS) {
            int r = idx >> 4, c4 = idx & 15;
            float4 v = Qg[r * 16 + c4];
            float* d = sm + QS_OFF + r * 66 + c4 * 4;
            d[0] = v.x; d[1] = v.y; d[2] = v.z; d[3] = v.w;
        }
    }

    ull O2[8];
    float m[8], l[8];
    #pragma unroll
    for (int i = 0; i < 8; i++) { m[i] = -1e30f; l[i] = 0.0f; O2[i] = 0ULL; }

    for (int kt = 0; kt < T_LEN / KT; kt++) {
        __syncthreads();
        {
            const float4* Kg = (const float4*)(Kp + (size_t)kt * KT * CH);
            const float4* Vg = (const float4*)(Vp + (size_t)kt * KT * CH);
            for (int idx = tid; idx < KT * 16; idx += FTHREADS) {
                int s = idx >> 4, c4 = idx & 15;
                int ps = s ^ (((s >> 5) & 3) << 1);
                float4 k = Kg[s * 16 + c4];
                float* kd = sm + KT_OFF + c4 * 4 * 130 + ps;
                kd[0] = k.x; kd[130] = k.y; kd[260] = k.z; kd[390] = k.w;
                float4 v = Vg[s * 16 + c4];
                float4 w = (c4 >= 8) ? make_float4(v.z, v.w, v.x, v.y) : v;
                *(float4*)(sm + V_OFF + s * 64 + c4 * 4) = w;
            }
        }
        __syncthreads();

        // ---- S = Q K^T ----
        ull S2[8][2];
        #pragma unroll
        for (int i = 0; i < 8; i++) { S2[i][0] = 0ULL; S2[i][1] = 0ULL; }

        const float* qb = sm + QS_OFF + r0 * 66;
        #pragma unroll 4
        for (int c = 0; c < CH; c += 2) {
            const float* kc0 = sm + KT_OFF + c * 130;
            const float* kc1 = kc0 + 130;
            ull ka0 = *(const ull*)(kc0 + pcol[0]);
            ull ka1 = *(const ull*)(kc0 + pcol[1]);
            ull kb0 = *(const ull*)(kc1 + pcol[0]);
            ull kb1 = *(const ull*)(kc1 + pcol[1]);
            #pragma unroll
            for (int i = 0; i < 8; i++) {
                float qa = qb[i * 66 + c], qv = qb[i * 66 + c + 1];
                ull qa2 = pk2(qa, qa), qv2 = pk2(qv, qv);
                S2[i][0] = fma2(qa2, ka0, S2[i][0]);
                S2[i][1] = fma2(qa2, ka1, S2[i][1]);
                S2[i][0] = fma2(qv2, kb0, S2[i][0]);
                S2[i][1] = fma2(qv2, kb1, S2[i][1]);
            }
        }

        // ---- online softmax (reduce over 32 lanes = full 128 cols) ----
        float sr[8][4];
        #pragma unroll
        for (int i = 0; i < 8; i++) {
            upk2(S2[i][0], sr[i][0], sr[i][1]);
            upk2(S2[i][1], sr[i][2], sr[i][3]);
        }
        #pragma unroll
        for (int i = 0; i < 8; i++) {
            float mx = fmaxf(fmaxf(sr[i][0], sr[i][1]), fmaxf(sr[i][2], sr[i][3]));
            #pragma unroll
            for (int off = 1; off < 32; off <<= 1) mx = fmaxf(mx, __shfl_xor_sync(0xffffffffu, mx, off));
            float mn = fmaxf(m[i], mx);
            float co = __expf(m[i] - mn);
            m[i] = mn;
            float rs = 0.0f;
            #pragma unroll
            for (int j = 0; j < 4; j++) { sr[i][j] = __expf(sr[i][j] - mn); rs += sr[i][j]; }
            #pragma unroll
            for (int off = 1; off < 32; off <<= 1) rs += __shfl_xor_sync(0xffffffffu, rs, off);
            l[i] = l[i] * co + rs;
            O2[i] = mul2(O2[i], pk2(co, co));
        }

        __syncthreads();   // QK reads of K done; stash P over K's smem
        #pragma unroll
        for (int i = 0; i < 8; i++) {
            *(ull*)(sm + KT_OFF + (r0 + i) * 130 + pcol[0]) = pk2(sr[i][0], sr[i][1]);
            *(ull*)(sm + KT_OFF + (r0 + i) * 130 + pcol[1]) = pk2(sr[i][2], sr[i][3]);
        }
        __syncthreads();

        // ---- O += P V ----
        #pragma unroll 4
        for (int s = 0; s < KT; s += 2) {
            int ps = s ^ (((s >> 5) & 3) << 1);
            ull v0 = *(const ull*)(sm + V_OFF + s * 64 + vch);
            ull v1 = *(const ull*)(sm + V_OFF + (s + 1) * 64 + vch);
            #pragma unroll
            for (int i = 0; i < 8; i++) {
                ull p2 = *(const ull*)(sm + KT_OFF + (r0 + i) * 130 + ps);
                float pl, ph; upk2(p2, pl, ph);
                O2[i] = fma2(pk2(pl, pl), v0, O2[i]);
                O2[i] = fma2(pk2(ph, ph), v1, O2[i]);
            }
        }
    }

    float* Op = g_anull + (size_t)bh * T_LEN * CH;
    #pragma unroll
    for (int i = 0; i < 8; i++) {
        float inv = 1.0f / l[i];
        float o0, o1; upk2(O2[i], o0, o1);
        *(ull*)(Op + (size_t)(q0 + r0 + i) * CH + ch0) = pk2(o0 * inv, o1 * inv);
    }
}

// foreground: per (b,obj) region-restricted attention, accumulated with atomics
__global__ __launch_bounds__(FTHREADS, 2)
void flash_fg_kernel() {
    extern __shared__ float sm[];
    const int bh = blockIdx.z;
    const int o  = blockIdx.y;
    const int b  = bh >> 3;
    const int* box = g_regbox + (b * NOBJ + o) * 4;
    const int i0 = box[0], i1 = box[1], j0 = box[2], j1 = box[3];
    const int rw = j1 - j0;
    const int nR = (i1 - i0) * rw;
    const int qbase = blockIdx.x * QT;
    if (qbase >= nR) return;

    const float* Qp = g_Qf + (size_t)bh * T_LEN * CH;
    const float* Kp = g_Kf + (size_t)bh * T_LEN * CH;
    const float* Vp = g_Vf + (size_t)bh * T_LEN * CH;
    const int tid = threadIdx.x;
    const int rowg = tid >> 5, colg = tid & 31;
    const int r0 = rowg * 8;
    const int s0 = colg * 4;
    const int ch0 = colg * 2;

    int pcol[2];
    #pragma unroll
    for (int j = 0; j < 2; j++) {
        int s = s0 + 2 * j;
        pcol[j] = s ^ (((s >> 5) & 3) << 1);
    }
    const int vch = ch0 ^ (((ch0 >> 5) & 1) << 1);

    // gather Q region tokens
    for (int idx = tid; idx < QT * 16; idx += FTHREADS) {
        int r = idx >> 4, c4 = idx & 15;
        int u = qbase + r;
        float4 v = make_float4(0.f, 0.f, 0.f, 0.f);
        if (u < nR) {
            int t = (i0 + u / rw) * 32 + j0 + u % rw;
            v = ((const float4*)(Qp + (size_t)t * CH))[c4];
        }
        float* d = sm + QS_OFF + r * 66 + c4 * 4;
        d[0] = v.x; d[1] = v.y; d[2] = v.z; d[3] = v.w;
    }

    ull O2[8];
    float m[8], l[8];
    #pragma unroll
    for (int i = 0; i < 8; i++) { m[i] = -1e30f; l[i] = 0.0f; O2[i] = 0ULL; }

    const int nkt = (nR + KT - 1) / KT;
    for (int kt = 0; kt < nkt; kt++) {
        __syncthreads();
        for (int idx = tid; idx < KT * 16; idx += FTHREADS) {
            int s = idx >> 4, c4 = idx & 15;
            int sg = kt * KT + s;
            float4 k = make_float4(0.f, 0.f, 0.f, 0.f);
            float4 v = k;
            if (sg < nR) {
                int t = (i0 + sg / rw) * 32 + j0 + sg % rw;
                k = ((const float4*)(Kp + (size_t)t * CH))[c4];
                v = ((const float4*)(Vp + (size_t)t * CH))[c4];
            }
            int ps = s ^ (((s >> 5) & 3) << 1);
            float* kd = sm + KT_OFF + c4 * 4 * 130 + ps;
            kd[0] = k.x; kd[130] = k.y; kd[260] = k.z; kd[390] = k.w;
            float4 w = (c4 >= 8) ? make_float4(v.z, v.w, v.x, v.y) : v;
            *(float4*)(sm + V_OFF + s * 64 + c4 * 4) = w;
        }
        __syncthreads();

        ull S2[8][2];
        #pragma unroll
        for (int i = 0; i < 8; i++) { S2[i][0] = 0ULL; S2[i][1] = 0ULL; }

        const float* qb = sm + QS_OFF + r0 * 66;
        #pragma unroll 4
        for (int c = 0; c < CH; c += 2) {
            const float* kc0 = sm + KT_OFF + c * 130;
            const float* kc1 = kc0 + 130;
            ull ka0 = *(const ull*)(kc0 + pcol[0]);
            ull ka1 = *(const ull*)(kc0 + pcol[1]);
            ull kb0 = *(const ull*)(kc1 + pcol[0]);
            ull kb1 = *(const ull*)(kc1 + pcol[1]);
            #pragma unroll
            for (int i = 0; i < 8; i++) {
                float qa = qb[i * 66 + c], qv = qb[i * 66 + c + 1];
                ull qa2 = pk2(qa, qa), qv2 = pk2(qv, qv);
                S2[i][0] = fma2(qa2, ka0, S2[i][0]);
                S2[i][1] = fma2(qa2, ka1, S2[i][1]);
                S2[i][0] = fma2(qv2, kb0, S2[i][0]);
                S2[i][1] = fma2(qv2, kb1, S2[i][1]);
            }
        }

        float sr[8][4];
        #pragma unroll
        for (int i = 0; i < 8; i++) {
            upk2(S2[i][0], sr[i][0], sr[i][1]);
            upk2(S2[i][1], sr[i][2], sr[i][3]);
        }
        // mask columns beyond region
        #pragma unroll
        for (int j = 0; j < 4; j++) {
            if (kt * KT + s0 + j >= nR) {
                #pragma unroll
                for (int i = 0; i < 8; i++) sr[i][j] = -1e30f;
            }
        }

        #pragma unroll
        for (int i = 0; i < 8; i++) {
            float mx = fmaxf(fmaxf(sr[i][0], sr[i][1]), fmaxf(sr[i][2], sr[i][3]));
            #pragma unroll
            for (int off = 1; off < 32; off <<= 1) mx = fmaxf(mx, __shfl_xor_sync(0xffffffffu, mx, off));
            float mn = fmaxf(m[i], mx);
            float co = __expf(m[i] - mn);
            m[i] = mn;
            float rs = 0.0f;
            #pragma unroll
            for (int j = 0; j < 4; j++) { sr[i][j] = __expf(sr[i][j] - mn); rs += sr[i][j]; }
            #pragma unroll
            for (int off = 1; off < 32; off <<= 1) rs += __shfl_xor_sync(0xffffffffu, rs, off);
            l[i] = l[i] * co + rs;
            O2[i] = mul2(O2[i], pk2(co, co));
        }

        __syncthreads();
        #pragma unroll
        for (int i = 0; i < 8; i++) {
            *(ull*)(sm + KT_OFF + (r0 + i) * 130 + pcol[0]) = pk2(sr[i][0], sr[i][1]);
            *(ull*)(sm + KT_OFF + (r0 + i) * 130 + pcol[1]) = pk2(sr[i][2], sr[i][3]);
        }
        __syncthreads();

        #pragma unroll 4
        for (int s = 0; s < KT; s += 2) {
            int ps = s ^ (((s >> 5) & 3) << 1);
            ull v0 = *(const ull*)(sm + V_OFF + s * 64 + vch);
            ull v1 = *(const ull*)(sm + V_OFF + (s + 1) * 64 + vch);
            #pragma unroll
            for (int i = 0; i < 8; i++) {
                ull p2 = *(const ull*)(sm + KT_OFF + (r0 + i) * 130 + ps);
                float pl, ph; upk2(p2, pl, ph);
                O2[i] = fma2(pk2(pl, pl), v0, O2[i]);
                O2[i] = fma2(pk2(ph, ph), v1, O2[i]);
            }
        }
    }

    float* Ap = g_afg + (size_t)bh * T_LEN * CH;
    #pragma unroll
    for (int i = 0; i < 8; i++) {
        int u = qbase + r0 + i;
        if (u < nR) {
            int t = (i0 + u / rw) * 32 + j0 + u % rw;
            float inv = 1.0f / l[i];
            float o0, o1; upk2(O2[i], o0, o1);
            float* dp = Ap + (size_t)t * CH + ch0;
            atomicAdd(dp + 0, o0 * inv);
            atomicAdd(dp + 1, o1 * inv);
        }
    }
}

// ---------------- finalize: select + divide + transpose to (bs, 512, T) ----------------
__global__ __launch_bounds__(256)
void finalize_kernel(float* __restrict__ out) {
    __shared__ float smf[64 * 65];
    const int bh = blockIdx.y;
    const int t0 = blockIdx.x * 64;
    const int b = bh >> 3, h = bh & 7;
    const float* An = g_anull + (size_t)bh * T_LEN * CH;
    const float* Af = g_afg   + (size_t)bh * T_LEN * CH;
    const float* Cn = g_cnt + b * T_LEN;
    const int tid = threadIdx.x;
    for (int i = tid; i < 4096; i += 256) {
        int tt = i >> 6, c = i & 63;
        int t = t0 + tt;
        float cnt = Cn[t];
        float v = (cnt > 0.5f) ? Af[(size_t)t * CH + c] / cnt : An[(size_t)t * CH + c];
        smf[tt * 65 + c] = v;
    }
    __syncthreads();
    float* op = out + (size_t)b * 512 * 1024 + (size_t)h * 64 * 1024 + t0;
    for (int i = tid; i < 4096; i += 256) {
        int c = i >> 6, tt = i & 63;
        op[(size_t)c * 1024 + tt] = smf[tt * 65 + c];
    }
}

// ---------------- launch ----------------
extern "C" void kernel_launch(void* const* d_in, const int* in_sizes, int n_in,
                              void* d_out, int out_size) {
    const float* qkv  = (const float*)d_in[0];
    const float* bb   = (const float*)d_in[1];
    const float* nemb = (const float*)d_in[2];
    const float* pemb = (const float*)d_in[3];
    const float* W    = (const float*)d_in[4];
    float* out = (float*)d_out;

    cudaFuncSetAttribute(flash_null_kernel, cudaFuncAttributeMaxDynamicSharedMemorySize, SMEM_BYTES);
    cudaFuncSetAttribute(flash_fg_kernel,   cudaFuncAttributeMaxDynamicSharedMemorySize, SMEM_BYTES);

    prep_kernel<<<1, 256>>>(bb);
    zero_afg_kernel<<<(HH_TOT * T_LEN * CH / 4 + 255) / 256, 256>>>();
    combine_kernel<<<dim3(24, 16, 8), 256>>>(qkv, nemb, pemb, W);
    flash_null_kernel<<<dim3(T_LEN / QT, HH_TOT), FTHREADS, SMEM_BYTES>>>();
    flash_fg_kernel<<<dim3(T_LEN / QT, NOBJ, HH_TOT), FTHREADS, SMEM_BYTES>>>();
    finalize_kernel<<<dim3(T_LEN / 64, HH_TOT), 256>>>(out);
}

// round 9
// speedup vs baseline: 1.1051x; 1.1051x over previous
#include <cuda_runtime.h>
#include <math.h>

// Problem constants (fixed shapes from setup_inputs)
#define BS      4
#define NHEAD   8
#define HH_TOT  32          // BS*NHEAD
#define T_LEN   1024
#define CH      64
#define NOBJ    8

// flash tile config (v4 core: reduction-paired f32x2, 128 threads)
#define QT      64          // q rows per block
#define KT      128         // k cols per tile
// smem (floats): Q[64][66] | K[128][66] (P[64][130] overlays) | Vt[64][130]
#define QS_OFF  0
#define KS_OFF  (64 * 66)                    // 4224
#define VT_OFF  (KS_OFF + 128 * 66)          // 12672
#define SMEM_FLOATS (VT_OFF + 64 * 130)      // 20992
#define SMEM_BYTES  (SMEM_FLOATS * 4)        // 83968

typedef unsigned long long ull;

// ---------------- f32x2 helpers ----------------
__device__ __forceinline__ ull pk2(float lo, float hi) {
    ull r; asm("mov.b64 %0, {%1, %2};" : "=l"(r) : "f"(lo), "f"(hi)); return r;
}
__device__ __forceinline__ void upk2(ull v, float& lo, float& hi) {
    asm("mov.b64 {%0, %1}, %2;" : "=f"(lo), "=f"(hi) : "l"(v));
}
__device__ __forceinline__ ull fma2(ull a, ull b, ull c) {
    ull d; asm("fma.rn.f32x2 %0, %1, %2, %3;" : "=l"(d) : "l"(a), "l"(b), "l"(c)); return d;
}
__device__ __forceinline__ ull mul2(ull a, ull b) {
    ull d; asm("mul.rn.f32x2 %0, %1, %2;" : "=l"(d) : "l"(a), "l"(b)); return d;
}

// ---------------- scratch (device globals; no allocs allowed) ----------------
__device__ float g_Qn[HH_TOT * T_LEN * CH];
__device__ float g_Kn[HH_TOT * T_LEN * CH];
__device__ float g_Vn[HH_TOT * T_LEN * CH];
__device__ float g_Qf[HH_TOT * T_LEN * CH];
__device__ float g_Kf[HH_TOT * T_LEN * CH];
__device__ float g_Vf[HH_TOT * T_LEN * CH];
__device__ float g_anull[HH_TOT * T_LEN * CH];
__device__ float g_afg[HH_TOT * T_LEN * CH];
__device__ int   g_regbox[BS * NOBJ * 4];   // i0,i1,j0,j1 (clamped to 32)
__device__ float g_cnt[BS * T_LEN];

// ---------------- init: zero a_fg everywhere; block 0 also does bbox prep ----------------
__global__ __launch_bounds__(256)
void init_kernel(const float* __restrict__ bb) {
    const int tid = threadIdx.x;
    // zero g_afg (graph-replay safe)
    {
        float4* p = (float4*)g_afg;
        for (int i = blockIdx.x * 256 + tid; i < (HH_TOT * T_LEN * CH) / 4; i += 256 * 256)
            p[i] = make_float4(0.f, 0.f, 0.f, 0.f);
    }
    if (blockIdx.x != 0) return;
    __shared__ int sreg[BS * NOBJ][4];
    if (tid < BS * NOBJ) {
        const float* p = bb + tid * 5;
        float x = p[0], y = p[1], w = p[2], h = p[3];
        int i0 = (int)fminf(31.0f, floorf(y * 32.0f));
        int j0 = (int)fminf(31.0f, floorf(x * 32.0f));
        int hh = (int)fmaxf(1.0f, ceilf(h * 32.0f));
        int ww = (int)fmaxf(1.0f, ceilf(w * 32.0f));
        int i1 = min(32, i0 + hh);
        int j1 = min(32, j0 + ww);
        g_regbox[tid * 4 + 0] = i0;  g_regbox[tid * 4 + 1] = i1;
        g_regbox[tid * 4 + 2] = j0;  g_regbox[tid * 4 + 3] = j1;
        sreg[tid][0] = i0; sreg[tid][1] = i1; sreg[tid][2] = j0; sreg[tid][3] = j1;
    }
    __syncthreads();
    for (int idx = tid; idx < BS * T_LEN; idx += 256) {
        int b = idx / T_LEN, t = idx % T_LEN;
        int i = t >> 5, j = t & 31;
        float c = 0.0f;
        #pragma unroll
        for (int o = 0; o < NOBJ; o++) {
            const int* r = sreg[b * NOBJ + o];
            if (i >= r[0] && i < r[1] && j >= r[2] && j < r[3]) c += 1.0f;
        }
        g_cnt[idx] = c;
    }
}

// ---------------- combine: qkv split + prompt projection GEMM (f32x2) ----------------
__global__ __launch_bounds__(256)
void combine_kernel(const float* __restrict__ qkv, const float* __restrict__ nemb,
                    const float* __restrict__ pemb, const float* __restrict__ W) {
    __shared__ float Ws[64 * 65];
    __shared__ __align__(16) float Es[64 * 68];
    const int g   = blockIdx.x;            // 0..23
    const int t0  = blockIdx.y * 64;
    const int zv  = blockIdx.z;
    const int b   = zv >> 1, var = zv & 1;
    const int head = g / 3, part = g % 3;
    const int cg0  = g * 64;
    const float* emb = (var ? pemb : nemb) + b * 64 * 1024;
    const int tid = threadIdx.x;

    for (int i = tid; i < 4096; i += 256) {
        int c = i >> 6, e = i & 63;
        Ws[c * 65 + e] = W[(cg0 + c) * 64 + e];
    }
    for (int i = tid; i < 4096; i += 256) {
        int e = i >> 6, t = i & 63;
        Es[e * 68 + t] = emb[e * 1024 + t0 + t];
    }
    __syncthreads();

    const int c = tid & 63, tg = tid >> 6;   // tg 0..3, 16 t each
    ull acc2[8];
    #pragma unroll
    for (int i = 0; i < 8; i++) acc2[i] = 0ULL;

    #pragma unroll 4
    for (int e = 0; e < 64; e++) {
        float w = Ws[c * 65 + e];
        ull w2 = pk2(w, w);
        const ull* row = (const ull*)(Es + e * 68 + tg * 16);
        #pragma unroll
        for (int k = 0; k < 8; k++) acc2[k] = fma2(w2, row[k], acc2[k]);
    }
    __syncthreads();
    const float* qk = qkv + (size_t)b * 1536 * 1024 + (size_t)cg0 * 1024 + t0;
    for (int i = tid; i < 4096; i += 256) {
        int cc = i >> 6, t = i & 63;
        Es[cc * 68 + t] = qk[cc * 1024 + t];
    }
    __syncthreads();

    float* dst;
    if (var == 0) dst = (part == 0 ? g_Qn : (part == 1 ? g_Kn : g_Vn));
    else          dst = (part == 0 ? g_Qf : (part == 1 ? g_Kf : g_Vf));
    dst += (b * NHEAD + head) * T_LEN * CH;
    const float sc = (part == 0) ? 0.125f : 1.0f;   // scale^2 folded into Q
    #pragma unroll
    for (int k = 0; k < 8; k++) {
        float a0, a1;
        upk2(acc2[k], a0, a1);
        int t = tg * 16 + 2 * k;
        dst[(t0 + t)     * CH + c] = (a0 + Es[c * 68 + t])     * sc;
        dst[(t0 + t + 1) * CH + c] = (a1 + Es[c * 68 + t + 1]) * sc;
    }
}

// ---------------- merged flash kernel (z=0: null, z=1..8: fg object z-1) ----------------
// 128 threads: rowg = tid>>4 (8 q-rows), colg = tid&15 (8 s-cols / 4 ch).
// QK pairs f32x2 along channels (reduction); PV pairs along s (reduction).
// No duplication MOVs anywhere in the hot loops.
__global__ __launch_bounds__(128)
void flash_kernel() {
    extern __shared__ float sm[];
    const int z  = blockIdx.z;
    const int bh = blockIdx.y;
    const int qbase = blockIdx.x * QT;
    int i0 = 0, j00 = 0, rw = 32, nR = T_LEN;
    const float *Qp, *Kp, *Vp;
    if (z == 0) {
        Qp = g_Qn + (size_t)bh * T_LEN * CH;
        Kp = g_Kn + (size_t)bh * T_LEN * CH;
        Vp = g_Vn + (size_t)bh * T_LEN * CH;
    } else {
        const int o = z - 1, b = bh >> 3;
        const int* box = g_regbox + (b * NOBJ + o) * 4;
        i0 = box[0]; j00 = box[2];
        rw = box[3] - j00;
        nR = (box[1] - i0) * rw;
        if (qbase >= nR) return;
        Qp = g_Qf + (size_t)bh * T_LEN * CH;
        Kp = g_Kf + (size_t)bh * T_LEN * CH;
        Vp = g_Vf + (size_t)bh * T_LEN * CH;
    }
    const int tid  = threadIdx.x;
    const int rowg = tid >> 4, colg = tid & 15;
    const int r0 = rowg * 8, s0 = colg * 8, ch0 = colg * 4;
    const int ksw = 2 * colg;                   // K ch-XOR (s>>3 == colg for this thread's cols)

    int pcol[4];                                 // P s-pair positions (r-major overlay swizzle)
    #pragma unroll
    for (int t = 0; t < 4; t++) {
        int s = s0 + 2 * t;
        pcol[t] = s ^ (((s >> 5) & 3) << 1);
    }

    // ---- load Q tile (gather; identity mapping for null) ----
    for (int idx = tid; idx < QT * 16; idx += 128) {
        int r = idx >> 4, c4 = idx & 15;
        int u = qbase + r;
        float4 v = make_float4(0.f, 0.f, 0.f, 0.f);
        if (u < nR) {
            int t = (z == 0) ? u : ((i0 + u / rw) * 32 + j00 + u % rw);
            v = ((const float4*)(Qp + (size_t)t * CH))[c4];
        }
        float* d = sm + QS_OFF + r * 66 + c4 * 4;
        d[0] = v.x; d[1] = v.y; d[2] = v.z; d[3] = v.w;
    }

    ull O2[8][4];                                // (even-s, odd-s) partial sums
    float m[8], l[8];
    #pragma unroll
    for (int i = 0; i < 8; i++) {
        m[i] = -1e30f; l[i] = 0.0f;
        #pragma unroll
        for (int k = 0; k < 4; k++) O2[i][k] = 0ULL;
    }

    const int nkt = (nR + KT - 1) / KT;
    for (int kt = 0; kt < nkt; kt++) {
        __syncthreads();
        // ---- load K (s-major, ch-XOR swizzled) and Vt (ch-major, s-XOR swizzled) ----
        for (int idx = tid; idx < KT * 16; idx += 128) {
            int s = idx >> 4, c4 = idx & 15;
            int sg = kt * KT + s;
            float4 k = make_float4(0.f, 0.f, 0.f, 0.f);
            float4 v = k;
            if (sg < nR) {
                int t = (z == 0) ? sg : ((i0 + sg / rw) * 32 + j00 + sg % rw);
                k = ((const float4*)(Kp + (size_t)t * CH))[c4];
                v = ((const float4*)(Vp + (size_t)t * CH))[c4];
            }
            int e = 2 * ((s >> 3) & 15);
            float* kr = sm + KS_OFF + s * 66;
            kr[(c4 * 4 + 0) ^ e] = k.x;
            kr[(c4 * 4 + 1) ^ e] = k.y;
            kr[(c4 * 4 + 2) ^ e] = k.z;
            kr[(c4 * 4 + 3) ^ e] = k.w;
            int ssw = s ^ (2 * c4);              // ch>>2 == c4 for these 4 channels
            sm[VT_OFF + (c4 * 4 + 0) * 130 + ssw] = v.x;
            sm[VT_OFF + (c4 * 4 + 1) * 130 + ssw] = v.y;
            sm[VT_OFF + (c4 * 4 + 2) * 130 + ssw] = v.z;
            sm[VT_OFF + (c4 * 4 + 3) * 130 + ssw] = v.w;
        }
        __syncthreads();

        // ---- S = Q K^T : f32x2 paired along channels ----
        ull S2[8][8];
        #pragma unroll
        for (int i = 0; i < 8; i++)
            #pragma unroll
            for (int j = 0; j < 8; j++) S2[i][j] = 0ULL;

        const float* qb = sm + QS_OFF + r0 * 66;
        #pragma unroll 4
        for (int c = 0; c < CH; c += 2) {
            const float* kc = sm + KS_OFF + s0 * 66 + (c ^ ksw);
            ull k2[8];
            #pragma unroll
            for (int j = 0; j < 8; j++) k2[j] = *(const ull*)(kc + j * 66);
            #pragma unroll
            for (int i = 0; i < 8; i++) {
                ull q2 = *(const ull*)(qb + i * 66 + c);
                #pragma unroll
                for (int j = 0; j < 8; j++) S2[i][j] = fma2(q2, k2[j], S2[i][j]);
            }
        }

        // ---- horizontal add + online softmax ----
        float sr[8][8];
        #pragma unroll
        for (int i = 0; i < 8; i++)
            #pragma unroll
            for (int j = 0; j < 8; j++) {
                float a, b; upk2(S2[i][j], a, b);
                sr[i][j] = a + b;
            }
        if (z != 0) {
            #pragma unroll
            for (int j = 0; j < 8; j++)
                if (kt * KT + s0 + j >= nR) {
                    #pragma unroll
                    for (int i = 0; i < 8; i++) sr[i][j] = -1e30f;
                }
        }
        #pragma unroll
        for (int i = 0; i < 8; i++) {
            float mx = sr[i][0];
            #pragma unroll
            for (int j = 1; j < 8; j++) mx = fmaxf(mx, sr[i][j]);
            #pragma unroll
            for (int off = 8; off; off >>= 1) mx = fmaxf(mx, __shfl_xor_sync(0xffffffffu, mx, off));
            float mn = fmaxf(m[i], mx);
            float co = __expf(m[i] - mn);
            m[i] = mn;
            float rs = 0.0f;
            #pragma unroll
            for (int j = 0; j < 8; j++) { sr[i][j] = __expf(sr[i][j] - mn); rs += sr[i][j]; }
            #pragma unroll
            for (int off = 8; off; off >>= 1) rs += __shfl_xor_sync(0xffffffffu, rs, off);
            l[i] = l[i] * co + rs;
            ull co2 = pk2(co, co);
            #pragma unroll
            for (int k = 0; k < 4; k++) O2[i][k] = mul2(O2[i][k], co2);
        }

        __syncthreads();                         // QK reads of K done; stash P over K's smem
        #pragma unroll
        for (int i = 0; i < 8; i++)
            #pragma unroll
            for (int t = 0; t < 4; t++)
                *(ull*)(sm + KS_OFF + (r0 + i) * 130 + pcol[t]) = pk2(sr[i][2 * t], sr[i][2 * t + 1]);
        __syncthreads();

        // ---- O += P V : f32x2 paired along s ----
        #pragma unroll 4
        for (int s = 0; s < KT; s += 2) {
            int ps = s ^ (((s >> 5) & 3) << 1);
            int ssw = s ^ (2 * colg);
            ull va[4];
            #pragma unroll
            for (int k = 0; k < 4; k++) va[k] = *(const ull*)(sm + VT_OFF + (ch0 + k) * 130 + ssw);
            #pragma unroll
            for (int i = 0; i < 8; i++) {
                ull p2 = *(const ull*)(sm + KS_OFF + (r0 + i) * 130 + ps);
                #pragma unroll
                for (int k = 0; k < 4; k++) O2[i][k] = fma2(p2, va[k], O2[i][k]);
            }
        }
    }

    // ---- epilogue: sum parities, normalize, store ----
    if (z == 0) {
        float* Op = g_anull + (size_t)bh * T_LEN * CH;
        #pragma unroll
        for (int i = 0; i < 8; i++) {
            float inv = 1.0f / l[i];
            float o[4];
            #pragma unroll
            for (int k = 0; k < 4; k++) {
                float a, b; upk2(O2[i][k], a, b);
                o[k] = (a + b) * inv;
            }
            *(float4*)(Op + (size_t)(qbase + r0 + i) * CH + ch0) =
                make_float4(o[0], o[1], o[2], o[3]);
        }
    } else {
        float* Ap = g_afg + (size_t)bh * T_LEN * CH;
        #pragma unroll
        for (int i = 0; i < 8; i++) {
            int u = qbase + r0 + i;
            if (u < nR) {
                int t = (i0 + u / rw) * 32 + j00 + u % rw;
                float inv = 1.0f / l[i];
                float* dp = Ap + (size_t)t * CH + ch0;
                #pragma unroll
                for (int k = 0; k < 4; k++) {
                    float a, b; upk2(O2[i][k], a, b);
                    atomicAdd(dp + k, (a + b) * inv);
                }
            }
        }
    }
}

// ---------------- finalize: select + divide + transpose to (bs, 512, T) ----------------
__global__ __launch_bounds__(256)
void finalize_kernel(float* __restrict__ out) {
    __shared__ float smf[64 * 65];
    const int bh = blockIdx.y;
    const int t0 = blockIdx.x * 64;
    const int b = bh >> 3, h = bh & 7;
    const float* An = g_anull + (size_t)bh * T_LEN * CH;
    const float* Af = g_afg   + (size_t)bh * T_LEN * CH;
    const float* Cn = g_cnt + b * T_LEN;
    const int tid = threadIdx.x;
    for (int i = tid; i < 4096; i += 256) {
        int tt = i >> 6, c = i & 63;
        int t = t0 + tt;
        float cnt = Cn[t];
        float v = (cnt > 0.5f) ? Af[(size_t)t * CH + c] / cnt : An[(size_t)t * CH + c];
        smf[tt * 65 + c] = v;
    }
    __syncthreads();
    float* op = out + (size_t)b * 512 * 1024 + (size_t)h * 64 * 1024 + t0;
    for (int i = tid; i < 4096; i += 256) {
        int c = i >> 6, tt = i & 63;
        op[(size_t)c * 1024 + tt] = smf[tt * 65 + c];
    }
}

// ---------------- launch ----------------
extern "C" void kernel_launch(void* const* d_in, const int* in_sizes, int n_in,
                              void* d_out, int out_size) {
    const float* qkv  = (const float*)d_in[0];
    const float* bb   = (const float*)d_in[1];
    const float* nemb = (const float*)d_in[2];
    const float* pemb = (const float*)d_in[3];
    const float* W    = (const float*)d_in[4];
    float* out = (float*)d_out;

    cudaFuncSetAttribute(flash_kernel, cudaFuncAttributeMaxDynamicSharedMemorySize, SMEM_BYTES);

    init_kernel<<<256, 256>>>(bb);
    combine_kernel<<<dim3(24, 16, 8), 256>>>(qkv, nemb, pemb, W);
    flash_kernel<<<dim3(T_LEN / QT, HH_TOT, 1 + NOBJ), 128, SMEM_BYTES>>>();
    finalize_kernel<<<dim3(T_LEN / 64, HH_TOT), 256>>>(out);
}

// round 10
// speedup vs baseline: 1.6978x; 1.5362x over previous
#include <cuda_runtime.h>
#include <math.h>

// Problem constants (fixed shapes from setup_inputs)
#define BS      4
#define NHEAD   8
#define HH_TOT  32          // BS*NHEAD
#define T_LEN   1024
#define CH      64
#define NOBJ    8

// flash tile config (v5: tf32 mma.sync core)
#define QT      64          // q rows per block
#define KT      128         // k cols per tile
// smem (floats/tf32 words): Q[64][68] | K[128][68] | Vt[64][132]
#define QS_OFF  0
#define KS_OFF  (64 * 68)                    // 4352
#define VT_OFF  (KS_OFF + 128 * 68)          // 13056
#define SMEM_FLOATS (VT_OFF + 64 * 132)      // 21504
#define SMEM_BYTES  (SMEM_FLOATS * 4)        // 86016

typedef unsigned long long ull;

// ---------------- helpers ----------------
__device__ __forceinline__ ull pk2(float lo, float hi) {
    ull r; asm("mov.b64 %0, {%1, %2};" : "=l"(r) : "f"(lo), "f"(hi)); return r;
}
__device__ __forceinline__ void upk2(ull v, float& lo, float& hi) {
    asm("mov.b64 {%0, %1}, %2;" : "=f"(lo), "=f"(hi) : "l"(v));
}
__device__ __forceinline__ ull fma2(ull a, ull b, ull c) {
    ull d; asm("fma.rn.f32x2 %0, %1, %2, %3;" : "=l"(d) : "l"(a), "l"(b), "l"(c)); return d;
}
__device__ __forceinline__ unsigned tf32r(float x) {
    unsigned u; asm("cvt.rna.tf32.f32 %0, %1;" : "=r"(u) : "f"(x)); return u;
}

#define MMA_TF32(D, a0, a1, a2, a3, b0, b1)                                    \
    asm volatile(                                                              \
        "mma.sync.aligned.m16n8k8.row.col.f32.tf32.tf32.f32 "                  \
        "{%0,%1,%2,%3}, {%4,%5,%6,%7}, {%8,%9}, {%0,%1,%2,%3};"                \
        : "+f"((D)[0]), "+f"((D)[1]), "+f"((D)[2]), "+f"((D)[3])               \
        : "r"(a0), "r"(a1), "r"(a2), "r"(a3), "r"(b0), "r"(b1))

// ---------------- scratch (device globals; no allocs allowed) ----------------
__device__ float g_Qn[HH_TOT * T_LEN * CH];
__device__ float g_Kn[HH_TOT * T_LEN * CH];
__device__ float g_Vn[HH_TOT * T_LEN * CH];
__device__ float g_Qf[HH_TOT * T_LEN * CH];
__device__ float g_Kf[HH_TOT * T_LEN * CH];
__device__ float g_Vf[HH_TOT * T_LEN * CH];
__device__ float g_anull[HH_TOT * T_LEN * CH];
__device__ float g_afg[HH_TOT * T_LEN * CH];
__device__ int   g_regbox[BS * NOBJ * 4];   // i0,i1,j0,j1 (clamped to 32)
__device__ float g_cnt[BS * T_LEN];

// ---------------- init: zero a_fg everywhere; block 0 also does bbox prep ----------------
__global__ __launch_bounds__(256)
void init_kernel(const float* __restrict__ bb) {
    const int tid = threadIdx.x;
    {
        float4* p = (float4*)g_afg;
        for (int i = blockIdx.x * 256 + tid; i < (HH_TOT * T_LEN * CH) / 4; i += 256 * 256)
            p[i] = make_float4(0.f, 0.f, 0.f, 0.f);
    }
    if (blockIdx.x != 0) return;
    __shared__ int sreg[BS * NOBJ][4];
    if (tid < BS * NOBJ) {
        const float* p = bb + tid * 5;
        float x = p[0], y = p[1], w = p[2], h = p[3];
        int i0 = (int)fminf(31.0f, floorf(y * 32.0f));
        int j0 = (int)fminf(31.0f, floorf(x * 32.0f));
        int hh = (int)fmaxf(1.0f, ceilf(h * 32.0f));
        int ww = (int)fmaxf(1.0f, ceilf(w * 32.0f));
        int i1 = min(32, i0 + hh);
        int j1 = min(32, j0 + ww);
        g_regbox[tid * 4 + 0] = i0;  g_regbox[tid * 4 + 1] = i1;
        g_regbox[tid * 4 + 2] = j0;  g_regbox[tid * 4 + 3] = j1;
        sreg[tid][0] = i0; sreg[tid][1] = i1; sreg[tid][2] = j0; sreg[tid][3] = j1;
    }
    __syncthreads();
    for (int idx = tid; idx < BS * T_LEN; idx += 256) {
        int b = idx / T_LEN, t = idx % T_LEN;
        int i = t >> 5, j = t & 31;
        float c = 0.0f;
        #pragma unroll
        for (int o = 0; o < NOBJ; o++) {
            const int* r = sreg[b * NOBJ + o];
            if (i >= r[0] && i < r[1] && j >= r[2] && j < r[3]) c += 1.0f;
        }
        g_cnt[idx] = c;
    }
}

// ---------------- combine: qkv split + prompt projection GEMM (f32x2) ----------------
__global__ __launch_bounds__(256)
void combine_kernel(const float* __restrict__ qkv, const float* __restrict__ nemb,
                    const float* __restrict__ pemb, const float* __restrict__ W) {
    __shared__ float Ws[64 * 65];
    __shared__ __align__(16) float Es[64 * 68];
    const int g   = blockIdx.x;            // 0..23
    const int t0  = blockIdx.y * 64;
    const int zv  = blockIdx.z;
    const int b   = zv >> 1, var = zv & 1;
    const int head = g / 3, part = g % 3;
    const int cg0  = g * 64;
    const float* emb = (var ? pemb : nemb) + b * 64 * 1024;
    const int tid = threadIdx.x;

    for (int i = tid; i < 4096; i += 256) {
        int c = i >> 6, e = i & 63;
        Ws[c * 65 + e] = W[(cg0 + c) * 64 + e];
    }
    for (int i = tid; i < 4096; i += 256) {
        int e = i >> 6, t = i & 63;
        Es[e * 68 + t] = emb[e * 1024 + t0 + t];
    }
    __syncthreads();

    const int c = tid & 63, tg = tid >> 6;   // tg 0..3, 16 t each
    ull acc2[8];
    #pragma unroll
    for (int i = 0; i < 8; i++) acc2[i] = 0ULL;

    #pragma unroll 4
    for (int e = 0; e < 64; e++) {
        float w = Ws[c * 65 + e];
        ull w2 = pk2(w, w);
        const ull* row = (const ull*)(Es + e * 68 + tg * 16);
        #pragma unroll
        for (int k = 0; k < 8; k++) acc2[k] = fma2(w2, row[k], acc2[k]);
    }
    __syncthreads();
    const float* qk = qkv + (size_t)b * 1536 * 1024 + (size_t)cg0 * 1024 + t0;
    for (int i = tid; i < 4096; i += 256) {
        int cc = i >> 6, t = i & 63;
        Es[cc * 68 + t] = qk[cc * 1024 + t];
    }
    __syncthreads();

    float* dst;
    if (var == 0) dst = (part == 0 ? g_Qn : (part == 1 ? g_Kn : g_Vn));
    else          dst = (part == 0 ? g_Qf : (part == 1 ? g_Kf : g_Vf));
    dst += (b * NHEAD + head) * T_LEN * CH;
    const float sc = (part == 0) ? 0.125f : 1.0f;   // scale^2 folded into Q
    #pragma unroll
    for (int k = 0; k < 8; k++) {
        float a0, a1;
        upk2(acc2[k], a0, a1);
        int t = tg * 16 + 2 * k;
        dst[(t0 + t)     * CH + c] = (a0 + Es[c * 68 + t])     * sc;
        dst[(t0 + t + 1) * CH + c] = (a1 + Es[c * 68 + t + 1]) * sc;
    }
}

// ---------------- merged flash kernel, tf32 mma.sync core ----------------
// z=0: null attention; z=1..8: fg object z-1 (region-restricted).
// 128 threads = 4 warps; warp w owns q-rows [16w, 16w+16).
// QK: m16n8k8 over 16 n-tiles x 8 k-steps. P stays in registers; PV A-frags
// are built with intra-warp shfls (no smem P, only 2 barriers per k-tile).
__global__ __launch_bounds__(128)
void flash_kernel() {
    extern __shared__ float sm[];
    const int z  = blockIdx.z;
    const int bh = blockIdx.y;
    const int qbase = blockIdx.x * QT;
    int i0 = 0, j00 = 0, rw = 32, nR = T_LEN;
    const float *Qp, *Kp, *Vp;
    if (z == 0) {
        Qp = g_Qn + (size_t)bh * T_LEN * CH;
        Kp = g_Kn + (size_t)bh * T_LEN * CH;
        Vp = g_Vn + (size_t)bh * T_LEN * CH;
    } else {
        const int o = z - 1, b = bh >> 3;
        const int* box = g_regbox + (b * NOBJ + o) * 4;
        i0 = box[0]; j00 = box[2];
        rw = box[3] - j00;
        nR = (box[1] - i0) * rw;
        if (qbase >= nR) return;
        Qp = g_Qf + (size_t)bh * T_LEN * CH;
        Kp = g_Kf + (size_t)bh * T_LEN * CH;
        Vp = g_Vf + (size_t)bh * T_LEN * CH;
    }
    const int tid  = threadIdx.x;
    const int w    = tid >> 5, lane = tid & 31;
    const int la   = lane & 3, lg = lane >> 2;

    unsigned* QsU = (unsigned*)(sm + QS_OFF);
    unsigned* KsU = (unsigned*)(sm + KS_OFF);
    unsigned* VtU = (unsigned*)(sm + VT_OFF);

    // ---- load Q tile (gather; tf32-rounded) ----
    for (int idx = tid; idx < QT * 16; idx += 128) {
        int r = idx >> 4, c4 = idx & 15;
        int u = qbase + r;
        float4 v = make_float4(0.f, 0.f, 0.f, 0.f);
        if (u < nR) {
            int t = (z == 0) ? u : ((i0 + u / rw) * 32 + j00 + u % rw);
            v = ((const float4*)(Qp + (size_t)t * CH))[c4];
        }
        unsigned* d = QsU + r * 68 + c4 * 4;
        d[0] = tf32r(v.x); d[1] = tf32r(v.y); d[2] = tf32r(v.z); d[3] = tf32r(v.w);
    }

    float o[8][4];
    #pragma unroll
    for (int nt = 0; nt < 8; nt++) { o[nt][0] = o[nt][1] = o[nt][2] = o[nt][3] = 0.0f; }
    float m_lo = -1e30f, m_hi = -1e30f, l_lo = 0.0f, l_hi = 0.0f;

    const int aoff_lo = (16 * w + lg) * 68 + la;
    const int aoff_hi = aoff_lo + 8 * 68;
    const int boff    = lg * 68 + la;
    const int srcA  = (lane & ~3) | (la >> 1);
    const int srcA2 = srcA + 2;

    const int nkt = (nR + KT - 1) / KT;
    for (int kt = 0; kt < nkt; kt++) {
        __syncthreads();
        // ---- load K (stride-68) and Vt (transposed, stride-132, XOR-swizzled) ----
        for (int idx = tid; idx < KT * 16; idx += 128) {
            int s = idx >> 4, c4 = idx & 15;
            int sg = kt * KT + s;
            float4 k = make_float4(0.f, 0.f, 0.f, 0.f);
            float4 v = k;
            if (sg < nR) {
                int t = (z == 0) ? sg : ((i0 + sg / rw) * 32 + j00 + sg % rw);
                k = ((const float4*)(Kp + (size_t)t * CH))[c4];
                v = ((const float4*)(Vp + (size_t)t * CH))[c4];
            }
            unsigned* kd = KsU + s * 68 + c4 * 4;
            kd[0] = tf32r(k.x); kd[1] = tf32r(k.y); kd[2] = tf32r(k.z); kd[3] = tf32r(k.w);
            int sx = s ^ (4 * (c4 >> 1));            // (ch>>3) = c4>>1 for these 4 ch
            VtU[(4 * c4 + 0) * 132 + sx] = tf32r(v.x);
            VtU[(4 * c4 + 1) * 132 + sx] = tf32r(v.y);
            VtU[(4 * c4 + 2) * 132 + sx] = tf32r(v.z);
            VtU[(4 * c4 + 3) * 132 + sx] = tf32r(v.w);
        }
        __syncthreads();

        // ---- S = Q K^T via mma (acc[nt] covers cols [8nt, 8nt+8)) ----
        float acc[16][4];
        #pragma unroll
        for (int nt = 0; nt < 16; nt++) { acc[nt][0] = acc[nt][1] = acc[nt][2] = acc[nt][3] = 0.0f; }
        #pragma unroll
        for (int ks = 0; ks < 8; ks++) {
            int kk = ks * 8;
            unsigned a0 = QsU[aoff_lo + kk];
            unsigned a1 = QsU[aoff_hi + kk];
            unsigned a2 = QsU[aoff_lo + kk + 4];
            unsigned a3 = QsU[aoff_hi + kk + 4];
            #pragma unroll
            for (int nt = 0; nt < 16; nt++) {
                unsigned b0 = KsU[boff + nt * (8 * 68) + kk];
                unsigned b1 = KsU[boff + nt * (8 * 68) + kk + 4];
                MMA_TF32(acc[nt], a0, a1, a2, a3, b0, b1);
            }
        }

        // ---- mask columns beyond region (fg only) ----
        if (z != 0) {
            #pragma unroll
            for (int nt = 0; nt < 16; nt++) {
                int sc = kt * KT + 8 * nt + 2 * la;
                if (sc >= nR)     { acc[nt][0] = -1e30f; acc[nt][2] = -1e30f; }
                if (sc + 1 >= nR) { acc[nt][1] = -1e30f; acc[nt][3] = -1e30f; }
            }
        }

        // ---- online softmax (rows lg / lg+8; reduce across quad lanes) ----
        float mx0 = -1e30f, mx1 = -1e30f;
        #pragma unroll
        for (int nt = 0; nt < 16; nt++) {
            mx0 = fmaxf(mx0, fmaxf(acc[nt][0], acc[nt][1]));
            mx1 = fmaxf(mx1, fmaxf(acc[nt][2], acc[nt][3]));
        }
        mx0 = fmaxf(mx0, __shfl_xor_sync(0xffffffffu, mx0, 1));
        mx0 = fmaxf(mx0, __shfl_xor_sync(0xffffffffu, mx0, 2));
        mx1 = fmaxf(mx1, __shfl_xor_sync(0xffffffffu, mx1, 1));
        mx1 = fmaxf(mx1, __shfl_xor_sync(0xffffffffu, mx1, 2));
        float mn0 = fmaxf(m_lo, mx0), mn1 = fmaxf(m_hi, mx1);
        float co0 = __expf(m_lo - mn0), co1 = __expf(m_hi - mn1);
        m_lo = mn0; m_hi = mn1;
        float rs0 = 0.0f, rs1 = 0.0f;
        #pragma unroll
        for (int nt = 0; nt < 16; nt++) {
            acc[nt][0] = __expf(acc[nt][0] - mn0); rs0 += acc[nt][0];
            acc[nt][1] = __expf(acc[nt][1] - mn0); rs0 += acc[nt][1];
            acc[nt][2] = __expf(acc[nt][2] - mn1); rs1 += acc[nt][2];
            acc[nt][3] = __expf(acc[nt][3] - mn1); rs1 += acc[nt][3];
        }
        rs0 += __shfl_xor_sync(0xffffffffu, rs0, 1);
        rs0 += __shfl_xor_sync(0xffffffffu, rs0, 2);
        rs1 += __shfl_xor_sync(0xffffffffu, rs1, 1);
        rs1 += __shfl_xor_sync(0xffffffffu, rs1, 2);
        l_lo = l_lo * co0 + rs0;
        l_hi = l_hi * co1 + rs1;
        #pragma unroll
        for (int nt = 0; nt < 8; nt++) {
            o[nt][0] *= co0; o[nt][1] *= co0;
            o[nt][2] *= co1; o[nt][3] *= co1;
        }

        // ---- O += P V : A-frags from S-frags via intra-warp shfl ----
        #pragma unroll
        for (int ks = 0; ks < 16; ks++) {
            int kk = ks * 8;
            float p0 = acc[ks][0], p1 = acc[ks][1], p2 = acc[ks][2], p3 = acc[ks][3];
            float t00 = __shfl_sync(0xffffffffu, p0, srcA);
            float t01 = __shfl_sync(0xffffffffu, p1, srcA);
            float t10 = __shfl_sync(0xffffffffu, p2, srcA);
            float t11 = __shfl_sync(0xffffffffu, p3, srcA);
            float t20 = __shfl_sync(0xffffffffu, p0, srcA2);
            float t21 = __shfl_sync(0xffffffffu, p1, srcA2);
            float t30 = __shfl_sync(0xffffffffu, p2, srcA2);
            float t31 = __shfl_sync(0xffffffffu, p3, srcA2);
            unsigned a0 = tf32r((la & 1) ? t01 : t00);
            unsigned a1 = tf32r((la & 1) ? t11 : t10);
            unsigned a2 = tf32r((la & 1) ? t21 : t20);
            unsigned a3 = tf32r((la & 1) ? t31 : t30);
            #pragma unroll
            for (int nt = 0; nt < 8; nt++) {
                int c0 = (kk + la) ^ (4 * nt);
                int c1 = (kk + la + 4) ^ (4 * nt);
                unsigned b0 = VtU[(8 * nt + lg) * 132 + c0];
                unsigned b1 = VtU[(8 * nt + lg) * 132 + c1];
                MMA_TF32(o[nt], a0, a1, a2, a3, b0, b1);
            }
        }
    }

    // ---- epilogue ----
    float inv0 = 1.0f / l_lo, inv1 = 1.0f / l_hi;
    int u_lo = qbase + 16 * w + lg;
    int u_hi = u_lo + 8;
    if (z == 0) {
        float* Op = g_anull + (size_t)bh * T_LEN * CH;
        #pragma unroll
        for (int nt = 0; nt < 8; nt++) {
            int ch = 8 * nt + 2 * la;
            *(float2*)(Op + (size_t)u_lo * CH + ch) = make_float2(o[nt][0] * inv0, o[nt][1] * inv0);
            *(float2*)(Op + (size_t)u_hi * CH + ch) = make_float2(o[nt][2] * inv1, o[nt][3] * inv1);
        }
    } else {
        float* Ap = g_afg + (size_t)bh * T_LEN * CH;
        int t_lo = 0, t_hi = 0;
        if (u_lo < nR) t_lo = (i0 + u_lo / rw) * 32 + j00 + u_lo % rw;
        if (u_hi < nR) t_hi = (i0 + u_hi / rw) * 32 + j00 + u_hi % rw;
        #pragma unroll
        for (int nt = 0; nt < 8; nt++) {
            int ch = 8 * nt + 2 * la;
            if (u_lo < nR) {
                atomicAdd(Ap + (size_t)t_lo * CH + ch,     o[nt][0] * inv0);
                atomicAdd(Ap + (size_t)t_lo * CH + ch + 1, o[nt][1] * inv0);
            }
            if (u_hi < nR) {
                atomicAdd(Ap + (size_t)t_hi * CH + ch,     o[nt][2] * inv1);
                atomicAdd(Ap + (size_t)t_hi * CH + ch + 1, o[nt][3] * inv1);
            }
        }
    }
}

// ---------------- finalize: select + divide + transpose to (bs, 512, T) ----------------
__global__ __launch_bounds__(256)
void finalize_kernel(float* __restrict__ out) {
    __shared__ float smf[64 * 65];
    const int bh = blockIdx.y;
    const int t0 = blockIdx.x * 64;
    const int b = bh >> 3, h = bh & 7;
    const float* An = g_anull + (size_t)bh * T_LEN * CH;
    const float* Af = g_afg   + (size_t)bh * T_LEN * CH;
    const float* Cn = g_cnt + b * T_LEN;
    const int tid = threadIdx.x;
    for (int i = tid; i < 4096; i += 256) {
        int tt = i >> 6, c = i & 63;
        int t = t0 + tt;
        float cnt = Cn[t];
        float v = (cnt > 0.5f) ? Af[(size_t)t * CH + c] / cnt : An[(size_t)t * CH + c];
        smf[tt * 65 + c] = v;
    }
    __syncthreads();
    float* op = out + (size_t)b * 512 * 1024 + (size_t)h * 64 * 1024 + t0;
    for (int i = tid; i < 4096; i += 256) {
        int c = i >> 6, tt = i & 63;
        op[(size_t)c * 1024 + tt] = smf[tt * 65 + c];
    }
}

// ---------------- launch ----------------
extern "C" void kernel_launch(void* const* d_in, const int* in_sizes, int n_in,
                              void* d_out, int out_size) {
    const float* qkv  = (const float*)d_in[0];
    const float* bb   = (const float*)d_in[1];
    const float* nemb = (const float*)d_in[2];
    const float* pemb = (const float*)d_in[3];
    const float* W    = (const float*)d_in[4];
    float* out = (float*)d_out;

    cudaFuncSetAttribute(flash_kernel, cudaFuncAttributeMaxDynamicSharedMemorySize, SMEM_BYTES);

    init_kernel<<<256, 256>>>(bb);
    combine_kernel<<<dim3(24, 16, 8), 256>>>(qkv, nemb, pemb, W);
    flash_kernel<<<dim3(T_LEN / QT, HH_TOT, 1 + NOBJ), 128, SMEM_BYTES>>>();
    finalize_kernel<<<dim3(T_LEN / 64, HH_TOT), 256>>>(out);
}

// round 11
// speedup vs baseline: 1.9681x; 1.1592x over previous
#include <cuda_runtime.h>
#include <math.h>

// Problem constants (fixed shapes from setup_inputs)
#define BS      4
#define NHEAD   8
#define HH_TOT  32          // BS*NHEAD
#define T_LEN   1024
#define CH      64
#define NOBJ    8

// flash tile config (v6: tf32 mma core, KT=64, 4 CTA/SM)
#define QT      64          // q rows per block
#define KT      64          // k cols per tile
// smem (tf32 words): Q[64][68] | K[64][68] | Vt[64][68]
#define QS_OFF  0
#define KS_OFF  (64 * 68)                    // 4352
#define VT_OFF  (KS_OFF + 64 * 68)           // 8704
#define SMEM_FLOATS (VT_OFF + 64 * 68)       // 13056
#define SMEM_BYTES  (SMEM_FLOATS * 4)        // 52224

typedef unsigned long long ull;

// ---------------- helpers ----------------
__device__ __forceinline__ ull pk2(float lo, float hi) {
    ull r; asm("mov.b64 %0, {%1, %2};" : "=l"(r) : "f"(lo), "f"(hi)); return r;
}
__device__ __forceinline__ void upk2(ull v, float& lo, float& hi) {
    asm("mov.b64 {%0, %1}, %2;" : "=f"(lo), "=f"(hi) : "l"(v));
}
__device__ __forceinline__ ull fma2(ull a, ull b, ull c) {
    ull d; asm("fma.rn.f32x2 %0, %1, %2, %3;" : "=l"(d) : "l"(a), "l"(b), "l"(c)); return d;
}
__device__ __forceinline__ unsigned tf32r(float x) {
    unsigned u; asm("cvt.rna.tf32.f32 %0, %1;" : "=r"(u) : "f"(x)); return u;
}
__device__ __forceinline__ float tf32f(float x) {          // round, keep as float bits
    unsigned u = tf32r(x); return __uint_as_float(u);
}

#define MMA_TF32(D, a0, a1, a2, a3, b0, b1)                                    \
    asm volatile(                                                              \
        "mma.sync.aligned.m16n8k8.row.col.f32.tf32.tf32.f32 "                  \
        "{%0,%1,%2,%3}, {%4,%5,%6,%7}, {%8,%9}, {%0,%1,%2,%3};"                \
        : "+f"((D)[0]), "+f"((D)[1]), "+f"((D)[2]), "+f"((D)[3])               \
        : "r"(a0), "r"(a1), "r"(a2), "r"(a3), "r"(b0), "r"(b1))

// ---------------- scratch (device globals; no allocs allowed) ----------------
__device__ float g_Qn[HH_TOT * T_LEN * CH];
__device__ float g_Kn[HH_TOT * T_LEN * CH];
__device__ float g_Vn[HH_TOT * T_LEN * CH];
__device__ float g_Qf[HH_TOT * T_LEN * CH];
__device__ float g_Kf[HH_TOT * T_LEN * CH];
__device__ float g_Vf[HH_TOT * T_LEN * CH];
__device__ float g_anull[HH_TOT * T_LEN * CH];
__device__ float g_afg[HH_TOT * T_LEN * CH];
__device__ int   g_regbox[BS * NOBJ * 4];   // i0,i1,j0,j1 (clamped to 32)
__device__ float g_cnt[BS * T_LEN];

// ---------------- init: zero a_fg everywhere; block 0 also does bbox prep ----------------
__global__ __launch_bounds__(256)
void init_kernel(const float* __restrict__ bb) {
    const int tid = threadIdx.x;
    {
        float4* p = (float4*)g_afg;
        for (int i = blockIdx.x * 256 + tid; i < (HH_TOT * T_LEN * CH) / 4; i += 256 * 256)
            p[i] = make_float4(0.f, 0.f, 0.f, 0.f);
    }
    if (blockIdx.x != 0) return;
    __shared__ int sreg[BS * NOBJ][4];
    if (tid < BS * NOBJ) {
        const float* p = bb + tid * 5;
        float x = p[0], y = p[1], w = p[2], h = p[3];
        int i0 = (int)fminf(31.0f, floorf(y * 32.0f));
        int j0 = (int)fminf(31.0f, floorf(x * 32.0f));
        int hh = (int)fmaxf(1.0f, ceilf(h * 32.0f));
        int ww = (int)fmaxf(1.0f, ceilf(w * 32.0f));
        int i1 = min(32, i0 + hh);
        int j1 = min(32, j0 + ww);
        g_regbox[tid * 4 + 0] = i0;  g_regbox[tid * 4 + 1] = i1;
        g_regbox[tid * 4 + 2] = j0;  g_regbox[tid * 4 + 3] = j1;
        sreg[tid][0] = i0; sreg[tid][1] = i1; sreg[tid][2] = j0; sreg[tid][3] = j1;
    }
    __syncthreads();
    for (int idx = tid; idx < BS * T_LEN; idx += 256) {
        int b = idx / T_LEN, t = idx % T_LEN;
        int i = t >> 5, j = t & 31;
        float c = 0.0f;
        #pragma unroll
        for (int o = 0; o < NOBJ; o++) {
            const int* r = sreg[b * NOBJ + o];
            if (i >= r[0] && i < r[1] && j >= r[2] && j < r[3]) c += 1.0f;
        }
        g_cnt[idx] = c;
    }
}

// ---------------- combine: qkv split + prompt projection GEMM (f32x2) ----------------
// Outputs are tf32-PRE-ROUNDED (rna) so the flash loader is cvt-free.
__global__ __launch_bounds__(256)
void combine_kernel(const float* __restrict__ qkv, const float* __restrict__ nemb,
                    const float* __restrict__ pemb, const float* __restrict__ W) {
    __shared__ float Ws[64 * 65];
    __shared__ __align__(16) float Es[64 * 68];
    const int g   = blockIdx.x;            // 0..23
    const int t0  = blockIdx.y * 64;
    const int zv  = blockIdx.z;
    const int b   = zv >> 1, var = zv & 1;
    const int head = g / 3, part = g % 3;
    const int cg0  = g * 64;
    const float* emb = (var ? pemb : nemb) + b * 64 * 1024;
    const int tid = threadIdx.x;

    for (int i = tid; i < 4096; i += 256) {
        int c = i >> 6, e = i & 63;
        Ws[c * 65 + e] = W[(cg0 + c) * 64 + e];
    }
    for (int i = tid; i < 4096; i += 256) {
        int e = i >> 6, t = i & 63;
        Es[e * 68 + t] = emb[e * 1024 + t0 + t];
    }
    __syncthreads();

    const int c = tid & 63, tg = tid >> 6;   // tg 0..3, 16 t each
    ull acc2[8];
    #pragma unroll
    for (int i = 0; i < 8; i++) acc2[i] = 0ULL;

    #pragma unroll 4
    for (int e = 0; e < 64; e++) {
        float w = Ws[c * 65 + e];
        ull w2 = pk2(w, w);
        const ull* row = (const ull*)(Es + e * 68 + tg * 16);
        #pragma unroll
        for (int k = 0; k < 8; k++) acc2[k] = fma2(w2, row[k], acc2[k]);
    }
    __syncthreads();
    const float* qk = qkv + (size_t)b * 1536 * 1024 + (size_t)cg0 * 1024 + t0;
    for (int i = tid; i < 4096; i += 256) {
        int cc = i >> 6, t = i & 63;
        Es[cc * 68 + t] = qk[cc * 1024 + t];
    }
    __syncthreads();

    float* dst;
    if (var == 0) dst = (part == 0 ? g_Qn : (part == 1 ? g_Kn : g_Vn));
    else          dst = (part == 0 ? g_Qf : (part == 1 ? g_Kf : g_Vf));
    dst += (b * NHEAD + head) * T_LEN * CH;
    const float sc = (part == 0) ? 0.125f : 1.0f;   // scale^2 folded into Q
    #pragma unroll
    for (int k = 0; k < 8; k++) {
        float a0, a1;
        upk2(acc2[k], a0, a1);
        int t = tg * 16 + 2 * k;
        dst[(t0 + t)     * CH + c] = tf32f((a0 + Es[c * 68 + t])     * sc);
        dst[(t0 + t + 1) * CH + c] = tf32f((a1 + Es[c * 68 + t + 1]) * sc);
    }
}

// ---------------- merged flash kernel, tf32 mma.sync core (KT=64) ----------------
// z=0: null attention; z=1..8: fg object z-1 (region-restricted).
// 128 threads = 4 warps; warp w owns q-rows [16w, 16w+16).
// Inputs pre-rounded to tf32 -> loader is pure LDG/STS.
__global__ __launch_bounds__(128, 4)
void flash_kernel() {
    extern __shared__ float sm[];
    const int z  = blockIdx.z;
    const int bh = blockIdx.y;
    const int qbase = blockIdx.x * QT;
    int i0 = 0, j00 = 0, rw = 32, nR = T_LEN;
    const float *Qp, *Kp, *Vp;
    if (z == 0) {
        Qp = g_Qn + (size_t)bh * T_LEN * CH;
        Kp = g_Kn + (size_t)bh * T_LEN * CH;
        Vp = g_Vn + (size_t)bh * T_LEN * CH;
    } else {
        const int o = z - 1, b = bh >> 3;
        const int* box = g_regbox + (b * NOBJ + o) * 4;
        i0 = box[0]; j00 = box[2];
        rw = box[3] - j00;
        nR = (box[1] - i0) * rw;
        if (qbase >= nR) return;
        Qp = g_Qf + (size_t)bh * T_LEN * CH;
        Kp = g_Kf + (size_t)bh * T_LEN * CH;
        Vp = g_Vf + (size_t)bh * T_LEN * CH;
    }
    const int tid  = threadIdx.x;
    const int w    = tid >> 5, lane = tid & 31;
    const int la   = lane & 3, lg = lane >> 2;

    unsigned* QsU = (unsigned*)(sm + QS_OFF);
    unsigned* KsU = (unsigned*)(sm + KS_OFF);
    unsigned* VtU = (unsigned*)(sm + VT_OFF);

    // ---- load Q tile (gather; already tf32) ----
    for (int idx = tid; idx < QT * 16; idx += 128) {
        int r = idx >> 4, c4 = idx & 15;
        int u = qbase + r;
        float4 v = make_float4(0.f, 0.f, 0.f, 0.f);
        if (u < nR) {
            int t = (z == 0) ? u : ((i0 + u / rw) * 32 + j00 + u % rw);
            v = ((const float4*)(Qp + (size_t)t * CH))[c4];
        }
        *(float4*)(sm + QS_OFF + r * 68 + c4 * 4) = v;
    }

    float o[8][4];
    #pragma unroll
    for (int nt = 0; nt < 8; nt++) { o[nt][0] = o[nt][1] = o[nt][2] = o[nt][3] = 0.0f; }
    float m_lo = -1e30f, m_hi = -1e30f, l_lo = 0.0f, l_hi = 0.0f;

    const int aoff_lo = (16 * w + lg) * 68 + la;
    const int aoff_hi = aoff_lo + 8 * 68;
    const int boff    = lg * 68 + la;
    const int srcA  = (lane & ~3) | (la >> 1);
    const int srcA2 = srcA + 2;

    const int nkt = (nR + KT - 1) / KT;
    for (int kt = 0; kt < nkt; kt++) {
        __syncthreads();
        // ---- load K (row-major stride 68) and Vt (transposed, XOR swizzle) ----
        for (int idx = tid; idx < KT * 16; idx += 128) {
            int s = idx >> 4, c4 = idx & 15;
            int sg = kt * KT + s;
            float4 k = make_float4(0.f, 0.f, 0.f, 0.f);
            float4 v = k;
            if (sg < nR) {
                int t = (z == 0) ? sg : ((i0 + sg / rw) * 32 + j00 + sg % rw);
                k = ((const float4*)(Kp + (size_t)t * CH))[c4];
                v = ((const float4*)(Vp + (size_t)t * CH))[c4];
            }
            *(float4*)(sm + KS_OFF + s * 68 + c4 * 4) = k;
            int sx = s ^ (4 * (c4 >> 1));            // ch>>3 == c4>>1
            float* vt = sm + VT_OFF;
            vt[(4 * c4 + 0) * 68 + sx] = v.x;
            vt[(4 * c4 + 1) * 68 + sx] = v.y;
            vt[(4 * c4 + 2) * 68 + sx] = v.z;
            vt[(4 * c4 + 3) * 68 + sx] = v.w;
        }
        __syncthreads();

        // ---- S = Q K^T via mma (acc[nt] covers cols [8nt, 8nt+8)) ----
        float acc[8][4];
        #pragma unroll
        for (int nt = 0; nt < 8; nt++) { acc[nt][0] = acc[nt][1] = acc[nt][2] = acc[nt][3] = 0.0f; }
        #pragma unroll
        for (int ks = 0; ks < 8; ks++) {
            int kk = ks * 8;
            unsigned a0 = QsU[aoff_lo + kk];
            unsigned a1 = QsU[aoff_hi + kk];
            unsigned a2 = QsU[aoff_lo + kk + 4];
            unsigned a3 = QsU[aoff_hi + kk + 4];
            #pragma unroll
            for (int nt = 0; nt < 8; nt++) {
                unsigned b0 = KsU[boff + nt * (8 * 68) + kk];
                unsigned b1 = KsU[boff + nt * (8 * 68) + kk + 4];
                MMA_TF32(acc[nt], a0, a1, a2, a3, b0, b1);
            }
        }

        // ---- mask columns beyond region (fg only) ----
        if (z != 0) {
            #pragma unroll
            for (int nt = 0; nt < 8; nt++) {
                int sc = kt * KT + 8 * nt + 2 * la;
                if (sc >= nR)     { acc[nt][0] = -1e30f; acc[nt][2] = -1e30f; }
                if (sc + 1 >= nR) { acc[nt][1] = -1e30f; acc[nt][3] = -1e30f; }
            }
        }

        // ---- online softmax (rows lg / lg+8; reduce across quad lanes) ----
        float mx0 = -1e30f, mx1 = -1e30f;
        #pragma unroll
        for (int nt = 0; nt < 8; nt++) {
            mx0 = fmaxf(mx0, fmaxf(acc[nt][0], acc[nt][1]));
            mx1 = fmaxf(mx1, fmaxf(acc[nt][2], acc[nt][3]));
        }
        mx0 = fmaxf(mx0, __shfl_xor_sync(0xffffffffu, mx0, 1));
        mx0 = fmaxf(mx0, __shfl_xor_sync(0xffffffffu, mx0, 2));
        mx1 = fmaxf(mx1, __shfl_xor_sync(0xffffffffu, mx1, 1));
        mx1 = fmaxf(mx1, __shfl_xor_sync(0xffffffffu, mx1, 2));
        float mn0 = fmaxf(m_lo, mx0), mn1 = fmaxf(m_hi, mx1);
        float co0 = __expf(m_lo - mn0), co1 = __expf(m_hi - mn1);
        m_lo = mn0; m_hi = mn1;
        float rs0 = 0.0f, rs1 = 0.0f;
        #pragma unroll
        for (int nt = 0; nt < 8; nt++) {
            acc[nt][0] = __expf(acc[nt][0] - mn0); rs0 += acc[nt][0];
            acc[nt][1] = __expf(acc[nt][1] - mn0); rs0 += acc[nt][1];
            acc[nt][2] = __expf(acc[nt][2] - mn1); rs1 += acc[nt][2];
            acc[nt][3] = __expf(acc[nt][3] - mn1); rs1 += acc[nt][3];
        }
        rs0 += __shfl_xor_sync(0xffffffffu, rs0, 1);
        rs0 += __shfl_xor_sync(0xffffffffu, rs0, 2);
        rs1 += __shfl_xor_sync(0xffffffffu, rs1, 1);
        rs1 += __shfl_xor_sync(0xffffffffu, rs1, 2);
        l_lo = l_lo * co0 + rs0;
        l_hi = l_hi * co1 + rs1;
        #pragma unroll
        for (int nt = 0; nt < 8; nt++) {
            o[nt][0] *= co0; o[nt][1] *= co0;
            o[nt][2] *= co1; o[nt][3] *= co1;
        }

        // ---- O += P V : A-frags from S-frags via intra-warp shfl ----
        #pragma unroll
        for (int ks = 0; ks < 8; ks++) {
            int kk = ks * 8;
            float p0 = acc[ks][0], p1 = acc[ks][1], p2 = acc[ks][2], p3 = acc[ks][3];
            float t00 = __shfl_sync(0xffffffffu, p0, srcA);
            float t01 = __shfl_sync(0xffffffffu, p1, srcA);
            float t10 = __shfl_sync(0xffffffffu, p2, srcA);
            float t11 = __shfl_sync(0xffffffffu, p3, srcA);
            float t20 = __shfl_sync(0xffffffffu, p0, srcA2);
            float t21 = __shfl_sync(0xffffffffu, p1, srcA2);
            float t30 = __shfl_sync(0xffffffffu, p2, srcA2);
            float t31 = __shfl_sync(0xffffffffu, p3, srcA2);
            unsigned a0 = tf32r((la & 1) ? t01 : t00);
            unsigned a1 = tf32r((la & 1) ? t11 : t10);
            unsigned a2 = tf32r((la & 1) ? t21 : t20);
            unsigned a3 = tf32r((la & 1) ? t31 : t30);
            #pragma unroll
            for (int nt = 0; nt < 8; nt++) {
                int c0 = (kk + la) ^ (4 * nt);
                int c1 = (kk + la + 4) ^ (4 * nt);
                unsigned b0 = VtU[(8 * nt + lg) * 68 + c0];
                unsigned b1 = VtU[(8 * nt + lg) * 68 + c1];
                MMA_TF32(o[nt], a0, a1, a2, a3, b0, b1);
            }
        }
    }

    // ---- epilogue ----
    float inv0 = 1.0f / l_lo, inv1 = 1.0f / l_hi;
    int u_lo = qbase + 16 * w + lg;
    int u_hi = u_lo + 8;
    if (z == 0) {
        float* Op = g_anull + (size_t)bh * T_LEN * CH;
        #pragma unroll
        for (int nt = 0; nt < 8; nt++) {
            int ch = 8 * nt + 2 * la;
            *(float2*)(Op + (size_t)u_lo * CH + ch) = make_float2(o[nt][0] * inv0, o[nt][1] * inv0);
            *(float2*)(Op + (size_t)u_hi * CH + ch) = make_float2(o[nt][2] * inv1, o[nt][3] * inv1);
        }
    } else {
        float* Ap = g_afg + (size_t)bh * T_LEN * CH;
        int t_lo = 0, t_hi = 0;
        if (u_lo < nR) t_lo = (i0 + u_lo / rw) * 32 + j00 + u_lo % rw;
        if (u_hi < nR) t_hi = (i0 + u_hi / rw) * 32 + j00 + u_hi % rw;
        #pragma unroll
        for (int nt = 0; nt < 8; nt++) {
            int ch = 8 * nt + 2 * la;
            if (u_lo < nR) {
                atomicAdd(Ap + (size_t)t_lo * CH + ch,     o[nt][0] * inv0);
                atomicAdd(Ap + (size_t)t_lo * CH + ch + 1, o[nt][1] * inv0);
            }
            if (u_hi < nR) {
                atomicAdd(Ap + (size_t)t_hi * CH + ch,     o[nt][2] * inv1);
                atomicAdd(Ap + (size_t)t_hi * CH + ch + 1, o[nt][3] * inv1);
            }
        }
    }
}

// ---------------- finalize: select + divide + transpose to (bs, 512, T) ----------------
__global__ __launch_bounds__(256)
void finalize_kernel(float* __restrict__ out) {
    __shared__ float smf[64 * 65];
    const int bh = blockIdx.y;
    const int t0 = blockIdx.x * 64;
    const int b = bh >> 3, h = bh & 7;
    const float* An = g_anull + (size_t)bh * T_LEN * CH;
    const float* Af = g_afg   + (size_t)bh * T_LEN * CH;
    const float* Cn = g_cnt + b * T_LEN;
    const int tid = threadIdx.x;
    for (int i = tid; i < 4096; i += 256) {
        int tt = i >> 6, c = i & 63;
        int t = t0 + tt;
        float cnt = Cn[t];
        float v = (cnt > 0.5f) ? Af[(size_t)t * CH + c] / cnt : An[(size_t)t * CH + c];
        smf[tt * 65 + c] = v;
    }
    __syncthreads();
    float* op = out + (size_t)b * 512 * 1024 + (size_t)h * 64 * 1024 + t0;
    for (int i = tid; i < 4096; i += 256) {
        int c = i >> 6, tt = i & 63;
        op[(size_t)c * 1024 + tt] = smf[tt * 65 + c];
    }
}

// ---------------- launch ----------------
extern "C" void kernel_launch(void* const* d_in, const int* in_sizes, int n_in,
                              void* d_out, int out_size) {
    const float* qkv  = (const float*)d_in[0];
    const float* bb   = (const float*)d_in[1];
    const float* nemb = (const float*)d_in[2];
    const float* pemb = (const float*)d_in[3];
    const float* W    = (const float*)d_in[4];
    float* out = (float*)d_out;

    cudaFuncSetAttribute(flash_kernel, cudaFuncAttributeMaxDynamicSharedMemorySize, SMEM_BYTES);

    init_kernel<<<256, 256>>>(bb);
    combine_kernel<<<dim3(24, 16, 8), 256>>>(qkv, nemb, pemb, W);
    flash_kernel<<<dim3(T_LEN / QT, HH_TOT, 1 + NOBJ), 128, SMEM_BYTES>>>();
    finalize_kernel<<<dim3(T_LEN / 64, HH_TOT), 256>>>(out);
}

// round 12
// speedup vs baseline: 2.3350x; 1.1864x over previous
#include <cuda_runtime.h>
#include <math.h>

// Problem constants (fixed shapes from setup_inputs)
#define BS      4
#define NHEAD   8
#define HH_TOT  32          // BS*NHEAD
#define T_LEN   1024
#define CH      64
#define NOBJ    8

// flash tile config (v7: tf32 mma core, KT=64, row-major V, cp.async)
#define QT      64          // q rows per block
#define KT      64          // k cols per tile
// smem (tf32 words): Q[64][68] | K[64][68] | V[64][72]
#define QS_OFF  0
#define KS_OFF  (64 * 68)                    // 4352
#define VS_OFF  (KS_OFF + 64 * 68)           // 8704
#define SMEM_FLOATS (VS_OFF + 64 * 72)       // 13312
#define SMEM_BYTES  (SMEM_FLOATS * 4)        // 53248

typedef unsigned long long ull;

// ---------------- helpers ----------------
__device__ __forceinline__ ull pk2(float lo, float hi) {
    ull r; asm("mov.b64 %0, {%1, %2};" : "=l"(r) : "f"(lo), "f"(hi)); return r;
}
__device__ __forceinline__ void upk2(ull v, float& lo, float& hi) {
    asm("mov.b64 {%0, %1}, %2;" : "=f"(lo), "=f"(hi) : "l"(v));
}
__device__ __forceinline__ ull fma2(ull a, ull b, ull c) {
    ull d; asm("fma.rn.f32x2 %0, %1, %2, %3;" : "=l"(d) : "l"(a), "l"(b), "l"(c)); return d;
}
__device__ __forceinline__ unsigned tf32r(float x) {
    unsigned u; asm("cvt.rna.tf32.f32 %0, %1;" : "=r"(u) : "f"(x)); return u;
}
__device__ __forceinline__ float tf32f(float x) {          // round, keep as float bits
    unsigned u = tf32r(x); return __uint_as_float(u);
}
__device__ __forceinline__ void cp16(unsigned dst, const void* src, int bytes) {
    asm volatile("cp.async.cg.shared.global [%0], [%1], 16, %2;"
                 :: "r"(dst), "l"(src), "r"(bytes));
}
#define CP_COMMIT() asm volatile("cp.async.commit_group;")
#define CP_WAIT0()  asm volatile("cp.async.wait_group 0;")

#define MMA_TF32(D, a0, a1, a2, a3, b0, b1)                                    \
    asm volatile(                                                              \
        "mma.sync.aligned.m16n8k8.row.col.f32.tf32.tf32.f32 "                  \
        "{%0,%1,%2,%3}, {%4,%5,%6,%7}, {%8,%9}, {%0,%1,%2,%3};"                \
        : "+f"((D)[0]), "+f"((D)[1]), "+f"((D)[2]), "+f"((D)[3])               \
        : "r"(a0), "r"(a1), "r"(a2), "r"(a3), "r"(b0), "r"(b1))

// ---------------- scratch (device globals; no allocs allowed) ----------------
__device__ float g_Qn[HH_TOT * T_LEN * CH];
__device__ float g_Kn[HH_TOT * T_LEN * CH];
__device__ float g_Vn[HH_TOT * T_LEN * CH];
__device__ float g_Qf[HH_TOT * T_LEN * CH];
__device__ float g_Kf[HH_TOT * T_LEN * CH];
__device__ float g_Vf[HH_TOT * T_LEN * CH];
__device__ float g_anull[HH_TOT * T_LEN * CH];
__device__ float g_afg[HH_TOT * T_LEN * CH];
__device__ int   g_regbox[BS * NOBJ * 4];   // i0,i1,j0,j1 (clamped to 32)
__device__ float g_cnt[BS * T_LEN];
__device__ int   g_nullskip[BS * 16];       // 1 if 64-token strip fully covered

// ---------------- init: zero a_fg; block 0 does bbox prep + counters + skip flags ----------------
__global__ __launch_bounds__(256)
void init_kernel(const float* __restrict__ bb) {
    const int tid = threadIdx.x;
    {
        float4* p = (float4*)g_afg;
        for (int i = blockIdx.x * 256 + tid; i < (HH_TOT * T_LEN * CH) / 4; i += 256 * 256)
            p[i] = make_float4(0.f, 0.f, 0.f, 0.f);
    }
    if (blockIdx.x != 0) return;
    __shared__ int sreg[BS * NOBJ][4];
    __shared__ float scnt[BS * T_LEN > 4096 ? 1 : BS * T_LEN];
    if (tid < BS * NOBJ) {
        const float* p = bb + tid * 5;
        float x = p[0], y = p[1], w = p[2], h = p[3];
        int i0 = (int)fminf(31.0f, floorf(y * 32.0f));
        int j0 = (int)fminf(31.0f, floorf(x * 32.0f));
        int hh = (int)fmaxf(1.0f, ceilf(h * 32.0f));
        int ww = (int)fmaxf(1.0f, ceilf(w * 32.0f));
        int i1 = min(32, i0 + hh);
        int j1 = min(32, j0 + ww);
        g_regbox[tid * 4 + 0] = i0;  g_regbox[tid * 4 + 1] = i1;
        g_regbox[tid * 4 + 2] = j0;  g_regbox[tid * 4 + 3] = j1;
        sreg[tid][0] = i0; sreg[tid][1] = i1; sreg[tid][2] = j0; sreg[tid][3] = j1;
    }
    __syncthreads();
    for (int idx = tid; idx < BS * T_LEN; idx += 256) {
        int b = idx / T_LEN, t = idx % T_LEN;
        int i = t >> 5, j = t & 31;
        float c = 0.0f;
        #pragma unroll
        for (int o = 0; o < NOBJ; o++) {
            const int* r = sreg[b * NOBJ + o];
            if (i >= r[0] && i < r[1] && j >= r[2] && j < r[3]) c += 1.0f;
        }
        g_cnt[idx] = c;
        scnt[idx] = c;
    }
    __syncthreads();
    if (tid < BS * 16) {
        int b = tid >> 4, qb = tid & 15;
        int flag = 1;
        for (int k = 0; k < 64; k++)
            if (scnt[b * T_LEN + qb * 64 + k] < 0.5f) { flag = 0; break; }
        g_nullskip[tid] = flag;
    }
}

// ---------------- combine: qkv split + prompt projection GEMM (f32x2) ----------------
// Outputs are tf32-PRE-ROUNDED (rna) so the flash loader is cvt-free.
__global__ __launch_bounds__(256)
void combine_kernel(const float* __restrict__ qkv, const float* __restrict__ nemb,
                    const float* __restrict__ pemb, const float* __restrict__ W) {
    __shared__ float Ws[64 * 65];
    __shared__ __align__(16) float Es[64 * 68];
    const int g   = blockIdx.x;            // 0..23
    const int t0  = blockIdx.y * 64;
    const int zv  = blockIdx.z;
    const int b   = zv >> 1, var = zv & 1;
    const int head = g / 3, part = g % 3;
    const int cg0  = g * 64;
    const float* emb = (var ? pemb : nemb) + b * 64 * 1024;
    const int tid = threadIdx.x;

    for (int i = tid; i < 4096; i += 256) {
        int c = i >> 6, e = i & 63;
        Ws[c * 65 + e] = W[(cg0 + c) * 64 + e];
    }
    for (int i = tid; i < 4096; i += 256) {
        int e = i >> 6, t = i & 63;
        Es[e * 68 + t] = emb[e * 1024 + t0 + t];
    }
    __syncthreads();

    const int c = tid & 63, tg = tid >> 6;   // tg 0..3, 16 t each
    ull acc2[8];
    #pragma unroll
    for (int i = 0; i < 8; i++) acc2[i] = 0ULL;

    #pragma unroll 4
    for (int e = 0; e < 64; e++) {
        float w = Ws[c * 65 + e];
        ull w2 = pk2(w, w);
        const ull* row = (const ull*)(Es + e * 68 + tg * 16);
        #pragma unroll
        for (int k = 0; k < 8; k++) acc2[k] = fma2(w2, row[k], acc2[k]);
    }
    __syncthreads();
    const float* qk = qkv + (size_t)b * 1536 * 1024 + (size_t)cg0 * 1024 + t0;
    for (int i = tid; i < 4096; i += 256) {
        int cc = i >> 6, t = i & 63;
        Es[cc * 68 + t] = qk[cc * 1024 + t];
    }
    __syncthreads();

    float* dst;
    if (var == 0) dst = (part == 0 ? g_Qn : (part == 1 ? g_Kn : g_Vn));
    else          dst = (part == 0 ? g_Qf : (part == 1 ? g_Kf : g_Vf));
    dst += (b * NHEAD + head) * T_LEN * CH;
    const float sc = (part == 0) ? 0.125f : 1.0f;   // scale^2 folded into Q
    #pragma unroll
    for (int k = 0; k < 8; k++) {
        float a0, a1;
        upk2(acc2[k], a0, a1);
        int t = tg * 16 + 2 * k;
        dst[(t0 + t)     * CH + c] = tf32f((a0 + Es[c * 68 + t])     * sc);
        dst[(t0 + t + 1) * CH + c] = tf32f((a1 + Es[c * 68 + t + 1]) * sc);
    }
}

// ---------------- merged flash kernel, tf32 mma.sync core (KT=64, cp.async) ----------------
// z=0: null attention; z=1..8: fg object z-1 (region-restricted).
// 128 threads = 4 warps; warp w owns q-rows [16w, 16w+16).
__global__ __launch_bounds__(128, 4)
void flash_kernel() {
    extern __shared__ float sm[];
    const int z  = blockIdx.z;
    const int bh = blockIdx.y;
    const int qbase = blockIdx.x * QT;
    int i0 = 0, j00 = 0, rw = 32, nR = T_LEN;
    const float *Qp, *Kp, *Vp;
    if (z == 0) {
        if (g_nullskip[(bh >> 3) * 16 + blockIdx.x]) return;   // a_null unused here
        Qp = g_Qn + (size_t)bh * T_LEN * CH;
        Kp = g_Kn + (size_t)bh * T_LEN * CH;
        Vp = g_Vn + (size_t)bh * T_LEN * CH;
    } else {
        const int o = z - 1, b = bh >> 3;
        const int* box = g_regbox + (b * NOBJ + o) * 4;
        i0 = box[0]; j00 = box[2];
        rw = box[3] - j00;
        nR = (box[1] - i0) * rw;
        if (qbase >= nR) return;
        Qp = g_Qf + (size_t)bh * T_LEN * CH;
        Kp = g_Kf + (size_t)bh * T_LEN * CH;
        Vp = g_Vf + (size_t)bh * T_LEN * CH;
    }
    const int tid  = threadIdx.x;
    const int w    = tid >> 5, lane = tid & 31;
    const int la   = lane & 3, lg = lane >> 2;

    unsigned* QsU = (unsigned*)(sm + QS_OFF);
    unsigned* KsU = (unsigned*)(sm + KS_OFF);
    unsigned* VsU = (unsigned*)(sm + VS_OFF);
    const unsigned smem_u = (unsigned)__cvta_generic_to_shared(sm);

    // ---- issue Q tile cp.asyncs (committed with tile 0) ----
    #pragma unroll
    for (int it = 0; it < 8; it++) {
        int idx = tid + it * 128;
        int r = idx >> 4, c4 = idx & 15;
        int u = qbase + r;
        const float* src = Qp;
        int bytes = 0;
        if (u < nR) {
            int t = (z == 0) ? u : ((i0 + u / rw) * 32 + j00 + u % rw);
            src = Qp + (size_t)t * CH + c4 * 4;
            bytes = 16;
        }
        cp16(smem_u + (QS_OFF + r * 68 + c4 * 4) * 4, src, bytes);
    }

    float o[8][4];
    #pragma unroll
    for (int nt = 0; nt < 8; nt++) { o[nt][0] = o[nt][1] = o[nt][2] = o[nt][3] = 0.0f; }
    float m_lo = -1e30f, m_hi = -1e30f, l_lo = 0.0f, l_hi = 0.0f;

    const int aoff_lo = (16 * w + lg) * 68 + la;
    const int aoff_hi = aoff_lo + 8 * 68;
    const int boff    = lg * 68 + la;          // K B-frag base (banks 4lg+la)
    const int voff    = la * 72 + lg;          // V B-frag base (banks 8la+lg)
    const int srcA  = (lane & ~3) | (la >> 1);
    const int srcA2 = srcA + 2;

    const int nkt = (nR + KT - 1) / KT;
    for (int kt = 0; kt < nkt; kt++) {
        __syncthreads();                        // prior-tile consumers done
        // ---- issue K/V tile cp.asyncs ----
        #pragma unroll
        for (int it = 0; it < 8; it++) {
            int idx = tid + it * 128;
            int s = idx >> 4, c4 = idx & 15;
            int sg = kt * KT + s;
            const float *ksrc = Kp, *vsrc = Vp;
            int bytes = 0;
            if (sg < nR) {
                int t = (z == 0) ? sg : ((i0 + sg / rw) * 32 + j00 + sg % rw);
                ksrc = Kp + (size_t)t * CH + c4 * 4;
                vsrc = Vp + (size_t)t * CH + c4 * 4;
                bytes = 16;
            }
            cp16(smem_u + (KS_OFF + s * 68 + c4 * 4) * 4, ksrc, bytes);
            cp16(smem_u + (VS_OFF + s * 72 + c4 * 4) * 4, vsrc, bytes);
        }
        CP_COMMIT();
        CP_WAIT0();
        __syncthreads();

        // ---- S = Q K^T via mma (acc[nt] covers cols [8nt, 8nt+8)) ----
        float acc[8][4];
        #pragma unroll
        for (int nt = 0; nt < 8; nt++) { acc[nt][0] = acc[nt][1] = acc[nt][2] = acc[nt][3] = 0.0f; }
        #pragma unroll
        for (int ks = 0; ks < 8; ks++) {
            int kk = ks * 8;
            unsigned a0 = QsU[aoff_lo + kk];
            unsigned a1 = QsU[aoff_hi + kk];
            unsigned a2 = QsU[aoff_lo + kk + 4];
            unsigned a3 = QsU[aoff_hi + kk + 4];
            #pragma unroll
            for (int nt = 0; nt < 8; nt++) {
                unsigned b0 = KsU[boff + nt * (8 * 68) + kk];
                unsigned b1 = KsU[boff + nt * (8 * 68) + kk + 4];
                MMA_TF32(acc[nt], a0, a1, a2, a3, b0, b1);
            }
        }

        // ---- mask columns beyond region (fg only) ----
        if (z != 0) {
            #pragma unroll
            for (int nt = 0; nt < 8; nt++) {
                int sc = kt * KT + 8 * nt + 2 * la;
                if (sc >= nR)     { acc[nt][0] = -1e30f; acc[nt][2] = -1e30f; }
                if (sc + 1 >= nR) { acc[nt][1] = -1e30f; acc[nt][3] = -1e30f; }
            }
        }

        // ---- online softmax (rows lg / lg+8; reduce across quad lanes) ----
        float mx0 = -1e30f, mx1 = -1e30f;
        #pragma unroll
        for (int nt = 0; nt < 8; nt++) {
            mx0 = fmaxf(mx0, fmaxf(acc[nt][0], acc[nt][1]));
            mx1 = fmaxf(mx1, fmaxf(acc[nt][2], acc[nt][3]));
        }
        mx0 = fmaxf(mx0, __shfl_xor_sync(0xffffffffu, mx0, 1));
        mx0 = fmaxf(mx0, __shfl_xor_sync(0xffffffffu, mx0, 2));
        mx1 = fmaxf(mx1, __shfl_xor_sync(0xffffffffu, mx1, 1));
        mx1 = fmaxf(mx1, __shfl_xor_sync(0xffffffffu, mx1, 2));
        float mn0 = fmaxf(m_lo, mx0), mn1 = fmaxf(m_hi, mx1);
        float co0 = __expf(m_lo - mn0), co1 = __expf(m_hi - mn1);
        m_lo = mn0; m_hi = mn1;
        float rs0 = 0.0f, rs1 = 0.0f;
        #pragma unroll
        for (int nt = 0; nt < 8; nt++) {
            acc[nt][0] = __expf(acc[nt][0] - mn0); rs0 += acc[nt][0];
            acc[nt][1] = __expf(acc[nt][1] - mn0); rs0 += acc[nt][1];
            acc[nt][2] = __expf(acc[nt][2] - mn1); rs1 += acc[nt][2];
            acc[nt][3] = __expf(acc[nt][3] - mn1); rs1 += acc[nt][3];
        }
        rs0 += __shfl_xor_sync(0xffffffffu, rs0, 1);
        rs0 += __shfl_xor_sync(0xffffffffu, rs0, 2);
        rs1 += __shfl_xor_sync(0xffffffffu, rs1, 1);
        rs1 += __shfl_xor_sync(0xffffffffu, rs1, 2);
        l_lo = l_lo * co0 + rs0;
        l_hi = l_hi * co1 + rs1;
        #pragma unroll
        for (int nt = 0; nt < 8; nt++) {
            o[nt][0] *= co0; o[nt][1] *= co0;
            o[nt][2] *= co1; o[nt][3] *= co1;
        }

        // ---- O += P V : A-frags via intra-warp shfl; B direct from row-major V ----
        #pragma unroll
        for (int ks = 0; ks < 8; ks++) {
            int kk = ks * 8;
            float p0 = acc[ks][0], p1 = acc[ks][1], p2 = acc[ks][2], p3 = acc[ks][3];
            float t00 = __shfl_sync(0xffffffffu, p0, srcA);
            float t01 = __shfl_sync(0xffffffffu, p1, srcA);
            float t10 = __shfl_sync(0xffffffffu, p2, srcA);
            float t11 = __shfl_sync(0xffffffffu, p3, srcA);
            float t20 = __shfl_sync(0xffffffffu, p0, srcA2);
            float t21 = __shfl_sync(0xffffffffu, p1, srcA2);
            float t30 = __shfl_sync(0xffffffffu, p2, srcA2);
            float t31 = __shfl_sync(0xffffffffu, p3, srcA2);
            unsigned a0 = tf32r((la & 1) ? t01 : t00);
            unsigned a1 = tf32r((la & 1) ? t11 : t10);
            unsigned a2 = tf32r((la & 1) ? t21 : t20);
            unsigned a3 = tf32r((la & 1) ? t31 : t30);
            const unsigned* vb = VsU + voff + kk * 72;
            #pragma unroll
            for (int nt = 0; nt < 8; nt++) {
                unsigned b0 = vb[8 * nt];
                unsigned b1 = vb[8 * nt + 4 * 72];
                MMA_TF32(o[nt], a0, a1, a2, a3, b0, b1);
            }
        }
    }

    // ---- epilogue ----
    float inv0 = 1.0f / l_lo, inv1 = 1.0f / l_hi;
    int u_lo = qbase + 16 * w + lg;
    int u_hi = u_lo + 8;
    if (z == 0) {
        float* Op = g_anull + (size_t)bh * T_LEN * CH;
        #pragma unroll
        for (int nt = 0; nt < 8; nt++) {
            int ch = 8 * nt + 2 * la;
            *(float2*)(Op + (size_t)u_lo * CH + ch) = make_float2(o[nt][0] * inv0, o[nt][1] * inv0);
            *(float2*)(Op + (size_t)u_hi * CH + ch) = make_float2(o[nt][2] * inv1, o[nt][3] * inv1);
        }
    } else {
        float* Ap = g_afg + (size_t)bh * T_LEN * CH;
        int t_lo = 0, t_hi = 0;
        if (u_lo < nR) t_lo = (i0 + u_lo / rw) * 32 + j00 + u_lo % rw;
        if (u_hi < nR) t_hi = (i0 + u_hi / rw) * 32 + j00 + u_hi % rw;
        #pragma unroll
        for (int nt = 0; nt < 8; nt++) {
            int ch = 8 * nt + 2 * la;
            if (u_lo < nR) {
                atomicAdd(Ap + (size_t)t_lo * CH + ch,     o[nt][0] * inv0);
                atomicAdd(Ap + (size_t)t_lo * CH + ch + 1, o[nt][1] * inv0);
            }
            if (u_hi < nR) {
                atomicAdd(Ap + (size_t)t_hi * CH + ch,     o[nt][2] * inv1);
                atomicAdd(Ap + (size_t)t_hi * CH + ch + 1, o[nt][3] * inv1);
            }
        }
    }
}

// ---------------- finalize: select + divide + transpose to (bs, 512, T) ----------------
__global__ __launch_bounds__(256)
void finalize_kernel(float* __restrict__ out) {
    __shared__ float smf[64 * 65];
    const int bh = blockIdx.y;
    const int t0 = blockIdx.x * 64;
    const int b = bh >> 3, h = bh & 7;
    const float* An = g_anull + (size_t)bh * T_LEN * CH;
    const float* Af = g_afg   + (size_t)bh * T_LEN * CH;
    const float* Cn = g_cnt + b * T_LEN;
    const int tid = threadIdx.x;
    for (int i = tid; i < 4096; i += 256) {
        int tt = i >> 6, c = i & 63;
        int t = t0 + tt;
        float cnt = Cn[t];
        float v = (cnt > 0.5f) ? Af[(size_t)t * CH + c] / cnt : An[(size_t)t * CH + c];
        smf[tt * 65 + c] = v;
    }
    __syncthreads();
    float* op = out + (size_t)b * 512 * 1024 + (size_t)h * 64 * 1024 + t0;
    for (int i = tid; i < 4096; i += 256) {
        int c = i >> 6, tt = i & 63;
        op[(size_t)c * 1024 + tt] = smf[tt * 65 + c];
    }
}

// ---------------- launch ----------------
extern "C" void kernel_launch(void* const* d_in, const int* in_sizes, int n_in,
                              void* d_out, int out_size) {
    const float* qkv  = (const float*)d_in[0];
    const float* bb   = (const float*)d_in[1];
    const float* nemb = (const float*)d_in[2];
    const float* pemb = (const float*)d_in[3];
    const float* W    = (const float*)d_in[4];
    float* out = (float*)d_out;

    cudaFuncSetAttribute(flash_kernel, cudaFuncAttributeMaxDynamicSharedMemorySize, SMEM_BYTES);

    init_kernel<<<256, 256>>>(bb);
    combine_kernel<<<dim3(24, 16, 8), 256>>>(qkv, nemb, pemb, W);
    flash_kernel<<<dim3(T_LEN / QT, HH_TOT, 1 + NOBJ), 128, SMEM_BYTES>>>();
    finalize_kernel<<<dim3(T_LEN / 64, HH_TOT), 256>>>(out);
}